// round 11
// baseline (speedup 1.0000x reference)
#include <cuda_runtime.h>

#define NMAX 50000
#define C 96

__device__ float g_v[NMAX * C];
__device__ float g_Q1[NMAX * 8];
__device__ float g_K1[NMAX * 8];
__device__ float4 g_c4[NMAX];

// ---- f32x2 packed-math helpers (sm_103a) ----
typedef unsigned long long ull;
#define FFMA2(d, a, b, c) \
    asm("fma.rn.f32x2 %0, %1, %2, %3;" : "=l"(d) : "l"(a), "l"(b), "l"(c))
#define LDS2X64(a, b, addr) \
    asm volatile("ld.shared.v2.u64 {%0, %1}, [%2];" : "=l"(a), "=l"(b) : "r"(addr))
#define LDS1X64(a, addr) \
    asm volatile("ld.shared.b64 %0, [%1];" : "=l"(a) : "r"(addr))
#define DUP2(d, f) \
    asm("mov.b64 %0, {%1, %1};" : "=l"(d) : "r"(__float_as_uint(f)))
#define UNPK(lo, hi, p) do { unsigned _ul, _uh; \
    asm("mov.b64 {%0, %1}, %2;" : "=r"(_ul), "=r"(_uh) : "l"(p)); \
    lo = __uint_as_float(_ul); hi = __uint_as_float(_uh); } while (0)
#define LANE_BAR(id) \
    asm volatile("bar.sync %0, 96;" :: "r"(id) : "memory")

__device__ __forceinline__ unsigned smaddr(const void* p) {
    unsigned r;
    asm("{.reg .u64 t; cvta.to.shared.u64 t, %1; cvt.u32.u64 %0, t;}"
        : "=r"(r) : "l"(p));
    return r;
}

// ---------------------------------------------------------------------------
// Kernel A (unchanged R10): v, Q1, K1; 64 rows/block, rows aliases Ws.
// ---------------------------------------------------------------------------
#define A_FEATT 0            // 96*68 = 6528
#define A_WS    6528         // 96*96 = 9216  (rows[64][100]=6400 aliases here)
#define A_W1T   15744        // Ww1fT[6][100] = 600
#define A_FLOATS 16344

__global__ __launch_bounds__(192) void qkv_kernel(
    const float* __restrict__ feat, const float* __restrict__ coord,
    const float* __restrict__ Wq, const float* __restrict__ bq,
    const float* __restrict__ gq, const float* __restrict__ betaq,
    const float* __restrict__ Wk, const float* __restrict__ bk,
    const float* __restrict__ gk, const float* __restrict__ betak,
    const float* __restrict__ Wv, const float* __restrict__ bv,
    const float* __restrict__ Ww1, const float* __restrict__ gw,
    int n)
{
    extern __shared__ float sm[];
    float* featT = sm + A_FEATT;
    float* Ws    = sm + A_WS;
    float* rows  = sm + A_WS;    // ALIAS
    float* Ww1fT = sm + A_W1T;
    const int tid = threadIdx.x;
    const int tx = tid % 24, ty = tid / 24;
    const int base = blockIdx.x * 64;

    if (tid < 64) {
        int row = base + tid;
        if (row < n) {
            float4 c;
            c.x = coord[row * 3 + 0];
            c.y = coord[row * 3 + 1];
            c.z = coord[row * 3 + 2];
            c.w = 0.f;
            g_c4[row] = c;
        }
    }

    for (int i = tid; i < 64 * 96; i += 192) {
        int r = i / 96, j = i % 96;
        featT[j * 68 + r] = (base + r < n) ? feat[(base + r) * 96 + j] : 0.f;
    }
    for (int i = tid; i < 600; i += 192) {
        int g = i / 100, c = i % 100;
        Ww1fT[i] = (c < 96) ? Ww1[c * 6 + g] * (gw[g] * rsqrtf(1.00001f)) : 0.f;
    }

    const unsigned fbase  = smaddr(featT) + 8 * ty * 4;
    const unsigned rows_b = smaddr(rows);
    const unsigned w1t_b  = smaddr(Ww1fT);

    for (int m = 0; m < 3; m++) {
        const float* W = (m == 0) ? Wq : ((m == 1) ? Wk : Wv);
        __syncthreads();
        for (int i = tid; i < 96 * 96; i += 192) Ws[i] = W[i];
        __syncthreads();

        ull acc2[4][4];
        #pragma unroll
        for (int p = 0; p < 4; p++)
            #pragma unroll
            for (int b = 0; b < 4; b++) acc2[p][b] = 0ULL;

        unsigned fa = fbase;
        #pragma unroll 4
        for (int j = 0; j < 96; j++) {
            ull f01, f23, f45, f67;
            LDS2X64(f01, f23, fa);
            LDS2X64(f45, f67, fa + 16);
            fa += 272;
            float4 w4 = *(const float4*)&Ws[j * 96 + 4 * tx];
            ull wd0, wd1, wd2, wd3;
            DUP2(wd0, w4.x); DUP2(wd1, w4.y); DUP2(wd2, w4.z); DUP2(wd3, w4.w);
            FFMA2(acc2[0][0], f01, wd0, acc2[0][0]);
            FFMA2(acc2[0][1], f01, wd1, acc2[0][1]);
            FFMA2(acc2[0][2], f01, wd2, acc2[0][2]);
            FFMA2(acc2[0][3], f01, wd3, acc2[0][3]);
            FFMA2(acc2[1][0], f23, wd0, acc2[1][0]);
            FFMA2(acc2[1][1], f23, wd1, acc2[1][1]);
            FFMA2(acc2[1][2], f23, wd2, acc2[1][2]);
            FFMA2(acc2[1][3], f23, wd3, acc2[1][3]);
            FFMA2(acc2[2][0], f45, wd0, acc2[2][0]);
            FFMA2(acc2[2][1], f45, wd1, acc2[2][1]);
            FFMA2(acc2[2][2], f45, wd2, acc2[2][2]);
            FFMA2(acc2[2][3], f45, wd3, acc2[2][3]);
            FFMA2(acc2[3][0], f67, wd0, acc2[3][0]);
            FFMA2(acc2[3][1], f67, wd1, acc2[3][1]);
            FFMA2(acc2[3][2], f67, wd2, acc2[3][2]);
            FFMA2(acc2[3][3], f67, wd3, acc2[3][3]);
        }

        float acc[8][4];
        #pragma unroll
        for (int p = 0; p < 4; p++)
            #pragma unroll
            for (int b = 0; b < 4; b++)
                UNPK(acc[2 * p][b], acc[2 * p + 1][b], acc2[p][b]);

        if (m == 2) {
            int c = 4 * tx;
            float4 bb = *(const float4*)&bv[c];
            #pragma unroll
            for (int a = 0; a < 8; a++) {
                int row = base + 8 * ty + a;
                if (row < n) {
                    float4 o = {acc[a][0] + bb.x, acc[a][1] + bb.y,
                                acc[a][2] + bb.z, acc[a][3] + bb.w};
                    *(float4*)&g_v[row * 96 + c] = o;
                }
            }
        } else {
            int c = 4 * tx;
            const float* bsrc = (m == 0) ? bq : bk;
            const float* gsrc = (m == 0) ? gq : gk;
            const float* besrc = (m == 0) ? betaq : betak;
            float4 bb = *(const float4*)&bsrc[c];
            float4 gg = *(const float4*)&gsrc[c];
            float4 be = *(const float4*)&besrc[c];
            float rs = rsqrtf(1.00001f);
            float aa[4] = {gg.x * rs, gg.y * rs, gg.z * rs, gg.w * rs};
            float bba[4] = {bb.x, bb.y, bb.z, bb.w};
            float bea[4] = {be.x, be.y, be.z, be.w};
            __syncthreads();
            #pragma unroll
            for (int a = 0; a < 8; a++) {
                float4 o;
                o.x = fmaxf((acc[a][0] + bba[0]) * aa[0] + bea[0], 0.f);
                o.y = fmaxf((acc[a][1] + bba[1]) * aa[1] + bea[1], 0.f);
                o.z = fmaxf((acc[a][2] + bba[2]) * aa[2] + bea[2], 0.f);
                o.w = fmaxf((acc[a][3] + bba[3]) * aa[3] + bea[3], 0.f);
                *(float4*)&rows[(8 * ty + a) * 100 + c] = o;
            }
            __syncthreads();
            float* dst = (m == 0) ? g_Q1 : g_K1;
            #pragma unroll
            for (int rr = 0; rr < 2; rr++) {
                int i = rr * 192 + tid;
                int r = i / 6, g = i % 6;
                ull a01 = 0ULL, a23 = 0ULL;
                unsigned rb = rows_b + r * 400;
                unsigned wb = w1t_b + g * 400;
                #pragma unroll
                for (int t = 0; t < 24; t++) {
                    ull r01, r23, w01, w23;
                    LDS2X64(r01, r23, rb); rb += 16;
                    LDS2X64(w01, w23, wb); wb += 16;
                    FFMA2(a01, r01, w01, a01);
                    FFMA2(a23, r23, w23, a23);
                }
                float l0, l1v, l2v, l3;
                UNPK(l0, l1v, a01); UNPK(l2v, l3, a23);
                if (base + r < n)
                    dst[(base + r) * 8 + g] = (l0 + l2v) + (l1v + l3);
            }
        }
    }
}

// ---------------------------------------------------------------------------
// Kernel B: fused attention. 384 threads = 4 point-lanes x 96.
// R10 + ph7 g-pair-per-warp (w bytes/thread 512B->128B) + de-padded pos +
// hoisted Wp1f + separate At buffer.
// ---------------------------------------------------------------------------
#define SH_WP2T 0        // [96][100]
#define SH_FT   9600     // [6][100]
#define SH_WP1F 10200    // [96][4]
#define SH_BP2  10584    // 96
#define SH_WW2  10680    // 40
#define SH_BW2  10720    // 8
#define SH_CB   10728    // 8
#define SH_W1F  10736    // 576
#define SH_PART 11312    // [16][96]
#define SH_LANE 12848
// per-lane (floats)
#define L_HT   0         // hT[16][100] = 1600
#define L_AT   1600      // At[6][100] = 600 -> pad 608  (separate, no alias)
#define L_PB   2208      // Pb[3][16][8] = 384
#define L_WH   2592      // whes[16][8] = 128
#define L_WP   2720      // wP[3 gpair][16 s] ull = 96 floats
#define L_POS  2816      // 2 x (posx16,posy16,posz16) = 96
#define L_MSK  2912      // 2 x 16 = 32
#define L_SW   2944      // 8
#define L_K1S  2952      // 2 x [16][8] = 256
#define L_IDX  3208      // 2 x 16 ints = 32
#define LZ     3240
#define B_FLOATS (SH_LANE + 4 * LZ)   // 25808 floats = 103232 B

__global__ __launch_bounds__(384, 2) void attn_kernel(
    const int* __restrict__ refidx,
    const float* __restrict__ Wp1, const float* __restrict__ bp1,
    const float* __restrict__ gp,  const float* __restrict__ betap,
    const float* __restrict__ Wp2, const float* __restrict__ bp2,
    const float* __restrict__ Ww1, const float* __restrict__ bw1,
    const float* __restrict__ gw,  const float* __restrict__ betaw,
    const float* __restrict__ Ww2, const float* __restrict__ bw2,
    float* __restrict__ out, int n)
{
    extern __shared__ float sm[];
    float* Wp2T  = sm + SH_WP2T;
    float* Fts   = sm + SH_FT;
    float* Wp1f  = sm + SH_WP1F;
    float* bp2s  = sm + SH_BP2;
    float* Ww2s  = sm + SH_WW2;
    float* bw2s  = sm + SH_BW2;
    float* CBs   = sm + SH_CB;
    float* Ww1fs = sm + SH_W1F;
    float* part  = sm + SH_PART;

    const int tid  = threadIdx.x;
    const int pp   = tid / 96;
    const int jr   = tid % 96;
    const int wl   = jr / 32;
    const int lane = tid & 31;
    const int sL   = jr & 15, gL = jr >> 4;
    const int barid = 1 + pp;

    float* lzone = sm + SH_LANE + pp * LZ;
    float* hT    = lzone + L_HT;
    float* At    = lzone + L_AT;
    float* Pb    = lzone + L_PB;
    float* whes  = lzone + L_WH;
    float* wPf   = lzone + L_WP;
    float* masks = lzone + L_MSK;
    float* swv   = lzone + L_SW;
    float* K1s   = lzone + L_K1S;
    int*   idxp  = (int*)(lzone + L_IDX);

    const unsigned sb     = smaddr(sm);
    const unsigned ht_b   = sb + 4 * (SH_LANE + pp * LZ + L_HT);
    const unsigned wp_b   = sb + 4 * (SH_LANE + pp * LZ + L_WP);
    const unsigned ft_b   = sb + 4 * SH_FT;
    const unsigned wp2_b  = sb + 4 * SH_WP2T;

    // ---- one-time staging ----
    for (int i = tid; i < 9216; i += 384)
        Wp2T[(i % 96) * 100 + i / 96] = Wp2[i];
    if (tid < 96) {
        float ap = gp[tid] * rsqrtf(1.00001f);
        Wp1f[tid * 4 + 0] = Wp1[tid]       * ap;
        Wp1f[tid * 4 + 1] = Wp1[96 + tid]  * ap;
        Wp1f[tid * 4 + 2] = Wp1[192 + tid] * ap;
        Wp1f[tid * 4 + 3] = bp1[tid] * ap + betap[tid];
        bp2s[tid] = bp2[tid];
    }
    if (tid < 36) Ww2s[tid] = Ww2[tid];
    if (tid < 6)  bw2s[tid] = bw2[tid];
    for (int i = tid; i < 576; i += 384) {
        int g = i % 6;
        Ww1fs[i] = Ww1[i] * (gw[g] * rsqrtf(1.00001f));
    }
    __syncthreads();
    for (int i = tid; i < 576; i += 384) {
        int j = i / 6, g = i % 6;
        float f = 0.f;
        #pragma unroll 8
        for (int c = 0; c < 96; c++) f += Wp2T[c * 100 + j] * Ww1fs[c * 6 + g];
        Fts[g * 100 + j] = f;
    }
    if (tid < 6) {
        float aw = gw[tid] * rsqrtf(1.00001f);
        float cb = bw1[tid] * aw + betaw[tid];
        for (int c = 0; c < 96; c++) cb += bp2s[c] * Ww1fs[c * 6 + tid];
        CBs[tid] = cb;
    }
    __syncthreads();

    // loop-invariant registers (Wp1f row for this thread's j)
    float4 wp = *(const float4*)&Wp1f[jr * 4];

    // ---- ph1 loader (warp0: pos/mask/idx; warp1: K1), buffer b ----
    auto load_ph1 = [&](int nn2, int b) {
        if (nn2 < n && lane < 16) {
            if (wl == 0) {
                int raw = refidx[nn2 * 16 + lane];
                int vv = raw + 1;
                masks[b * 16 + lane] = (vv > 0) ? 1.f : ((vv < 0) ? -1.f : 0.f);
                int idx = (raw < 0) ? raw + n : raw;
                idxp[b * 16 + lane] = idx;
                float4 c0 = g_c4[nn2];
                float4 cn = g_c4[idx];
                float* posb = lzone + L_POS + b * 48;
                posb[lane]      = cn.x - c0.x;
                posb[16 + lane] = cn.y - c0.y;
                posb[32 + lane] = cn.z - c0.z;
            } else if (wl == 1) {
                int raw = refidx[nn2 * 16 + lane];
                int idx = (raw < 0) ? raw + n : raw;
                float4 ka = *(const float4*)&g_K1[idx * 8];
                float4 kb = *(const float4*)&g_K1[idx * 8 + 4];
                *(float4*)&K1s[b * 128 + lane * 8] = ka;
                *(float4*)&K1s[b * 128 + lane * 8 + 4] = kb;
            }
        }
    };

    load_ph1(blockIdx.x * 4 + pp, 0);

    int par = 0;
    for (int it = blockIdx.x; it * 4 < n; it += gridDim.x) {
        int nn = it * 4 + pp;
        bool act = (nn < n);

        LANE_BAR(barid);   // ph1[par] visible to this lane

        // ---- ph2: h[s,j] -> hT (scalar pos reads) ----
        if (act) {
            const float* posb = lzone + L_POS + par * 48;
            #pragma unroll
            for (int s = 0; s < 16; s++) {
                float px = posb[s], py = posb[16 + s], pz = posb[32 + s];
                float hv = fmaxf(wp.w + px * wp.x + py * wp.y + pz * wp.z, 0.f);
                hT[s * 100 + jr] = hv;
            }
        }
        __syncwarp();   // ph3 reads only this warp's hT columns

        // ---- ph3: l1 partials, j-split across warps ----
        if (act) {
            int s = lane & 15, gt = lane >> 4;
            int j0 = 32 * wl;
            ull ag0 = 0ULL, ag1 = 0ULL, ag2 = 0ULL;
            unsigned hb  = ht_b + (s * 100 + j0) * 4;
            unsigned f0b = ft_b + ((gt * 3 + 0) * 100 + j0) * 4;
            unsigned f1b = f0b + 400;
            unsigned f2b = f1b + 400;
            #pragma unroll
            for (int t = 0; t < 8; t++) {
                ull h01, h23, f01, f23;
                LDS2X64(h01, h23, hb); hb += 16;
                LDS2X64(f01, f23, f0b); f0b += 16;
                FFMA2(ag0, h01, f01, ag0);
                FFMA2(ag0, h23, f23, ag0);
                LDS2X64(f01, f23, f1b); f1b += 16;
                FFMA2(ag1, h01, f01, ag1);
                FFMA2(ag1, h23, f23, ag1);
                LDS2X64(f01, f23, f2b); f2b += 16;
                FFMA2(ag2, h01, f01, ag2);
                FFMA2(ag2, h23, f23, ag2);
            }
            float x0, x1;
            float* pb = Pb + wl * 128 + s * 8 + gt * 4;
            UNPK(x0, x1, ag0); pb[0] = x0 + x1;
            UNPK(x0, x1, ag1); pb[1] = x0 + x1;
            UNPK(x0, x1, ag2); pb[2] = x0 + x1;
        }
        LANE_BAR(barid);

        // ---- ph3b: combine partials + K1/Q1, wh = relu(l1) ----
        if (act) {
            int slot = gL + (gL >= 3 ? 1 : 0);
            float l1 = CBs[gL] + K1s[par * 128 + sL * 8 + gL] - g_Q1[nn * 8 + gL]
                     + Pb[0 * 128 + sL * 8 + slot]
                     + Pb[1 * 128 + sL * 8 + slot]
                     + Pb[2 * 128 + sL * 8 + slot];
            whes[sL * 8 + gL] = fmaxf(l1, 0.f);
        }
        LANE_BAR(barid);

        // ---- ph456: l2, 16-lane softmax, masked weights -> wP packed pairs ----
        if (act) {
            float l2 = bw2s[gL];
            #pragma unroll
            for (int gg = 0; gg < 6; gg++)
                l2 += whes[sL * 8 + gg] * Ww2s[gg * 6 + gL];
            float mx = l2;
            #pragma unroll
            for (int off = 8; off >= 1; off >>= 1)
                mx = fmaxf(mx, __shfl_xor_sync(0xffffffffu, mx, off, 16));
            float e  = __expf(l2 - mx);
            float em = e * masks[par * 16 + sL];
            float ss = e, ms = em;
            #pragma unroll
            for (int off = 8; off >= 1; off >>= 1) {
                ss += __shfl_xor_sync(0xffffffffu, ss, off, 16);
                ms += __shfl_xor_sync(0xffffffffu, ms, off, 16);
            }
            float w = em / ss;
            wPf[(gL >> 1) * 32 + sL * 2 + (gL & 1)] = w;
            if (sL == 0) swv[gL] = ms / ss;
        }
        LANE_BAR(barid);

        // ---- prefetch next iteration's ph1 (overlaps ph7/8) ----
        load_ph1((it + gridDim.x) * 4 + pp, par ^ 1);

        // ---- ph7: A[j,g] = sum_s h[s,j] w[s,g].
        //      Warp wl owns g-pair wl for ALL 96 j (3 chunks of 32).
        //      w read as packed pair (8B) per s; h scalar per chunk. ----
        if (act) {
            ull A2c0 = 0ULL, A2c1 = 0ULL, A2c2 = 0ULL;
            unsigned wpa = wp_b + wl * 128;
            #pragma unroll
            for (int s = 0; s < 16; s++) {
                ull wpair;
                LDS1X64(wpair, wpa + s * 8);
                float h0 = hT[s * 100 + lane];
                float h1 = hT[s * 100 + 32 + lane];
                float h2 = hT[s * 100 + 64 + lane];
                ull hd0, hd1, hd2;
                DUP2(hd0, h0); DUP2(hd1, h1); DUP2(hd2, h2);
                FFMA2(A2c0, hd0, wpair, A2c0);
                FFMA2(A2c1, hd1, wpair, A2c1);
                FFMA2(A2c2, hd2, wpair, A2c2);
            }
            float alo, ahi;
            UNPK(alo, ahi, A2c0);
            At[(2 * wl) * 100 + lane]           = alo;
            At[(2 * wl + 1) * 100 + lane]       = ahi;
            UNPK(alo, ahi, A2c1);
            At[(2 * wl) * 100 + 32 + lane]      = alo;
            At[(2 * wl + 1) * 100 + 32 + lane]  = ahi;
            UNPK(alo, ahi, A2c2);
            At[(2 * wl) * 100 + 64 + lane]      = alo;
            At[(2 * wl + 1) * 100 + 64 + lane]  = ahi;
        }
        __syncthreads();   // cross-lane: ph8a reads all lanes' At

        // ---- ph8a: quartered Wp2^T @ A across 4 points (f32x2) ----
        {
            int c = jr, g = jr >> 4, j0 = pp * 24;
            ull pt2[4] = {0ULL, 0ULL, 0ULL, 0ULL};
            unsigned wb = wp2_b + (c * 100 + j0) * 4;
            unsigned ab0 = sb + 4 * (SH_LANE + 0 * LZ + L_AT) + (g * 100 + j0) * 4;
            unsigned ab1 = sb + 4 * (SH_LANE + 1 * LZ + L_AT) + (g * 100 + j0) * 4;
            unsigned ab2 = sb + 4 * (SH_LANE + 2 * LZ + L_AT) + (g * 100 + j0) * 4;
            unsigned ab3 = sb + 4 * (SH_LANE + 3 * LZ + L_AT) + (g * 100 + j0) * 4;
            #pragma unroll
            for (int t = 0; t < 6; t++) {
                ull w01, w23, a01, a23;
                LDS2X64(w01, w23, wb); wb += 16;
                LDS2X64(a01, a23, ab0); ab0 += 16;
                FFMA2(pt2[0], w01, a01, pt2[0]);
                FFMA2(pt2[0], w23, a23, pt2[0]);
                LDS2X64(a01, a23, ab1); ab1 += 16;
                FFMA2(pt2[1], w01, a01, pt2[1]);
                FFMA2(pt2[1], w23, a23, pt2[1]);
                LDS2X64(a01, a23, ab2); ab2 += 16;
                FFMA2(pt2[2], w01, a01, pt2[2]);
                FFMA2(pt2[2], w23, a23, pt2[2]);
                LDS2X64(a01, a23, ab3); ab3 += 16;
                FFMA2(pt2[3], w01, a01, pt2[3]);
                FFMA2(pt2[3], w23, a23, pt2[3]);
            }
            #pragma unroll
            for (int p = 0; p < 4; p++) {
                float lo, hi;
                UNPK(lo, hi, pt2[p]);
                part[(pp * 4 + p) * 96 + c] = lo + hi;
            }
        }
        __syncthreads();   // cross-lane: ph8b reads all lanes' part

        // ---- ph8b: combine quarters + v-gather term, store out ----
        if (act) {
            int c = jr, g = jr >> 4;
            const int* idq = (const int*)(lzone + L_IDX) + par * 16;
            float o = bp2s[c] * swv[g];
            o += part[(0 * 4 + pp) * 96 + c] + part[(1 * 4 + pp) * 96 + c]
               + part[(2 * 4 + pp) * 96 + c] + part[(3 * 4 + pp) * 96 + c];
            float vv[16];
            #pragma unroll
            for (int s = 0; s < 16; s++)
                vv[s] = g_v[idq[s] * 96 + c];
            const int wbase = (g >> 1) * 32 + (g & 1);
            #pragma unroll
            for (int s = 0; s < 16; s++)
                o += vv[s] * wPf[wbase + s * 2];
            out[nn * 96 + c] = o;
        }
        par ^= 1;
    }
}

extern "C" void kernel_launch(void* const* d_in, const int* in_sizes, int n_in,
                              void* d_out, int out_size) {
    const float* feat  = (const float*)d_in[0];
    const float* coord = (const float*)d_in[1];
    const int*   ref   = (const int*)d_in[2];
    const float* Wq    = (const float*)d_in[3];
    const float* bq    = (const float*)d_in[4];
    const float* gq    = (const float*)d_in[5];
    const float* betaq = (const float*)d_in[6];
    const float* Wk    = (const float*)d_in[7];
    const float* bk    = (const float*)d_in[8];
    const float* gk    = (const float*)d_in[9];
    const float* betak = (const float*)d_in[10];
    const float* Wv    = (const float*)d_in[11];
    const float* bv    = (const float*)d_in[12];
    const float* Wp1   = (const float*)d_in[13];
    const float* bp1   = (const float*)d_in[14];
    const float* gp    = (const float*)d_in[15];
    const float* betap = (const float*)d_in[16];
    const float* Wp2   = (const float*)d_in[17];
    const float* bp2   = (const float*)d_in[18];
    const float* Ww1   = (const float*)d_in[19];
    const float* bw1   = (const float*)d_in[20];
    const float* gw    = (const float*)d_in[21];
    const float* betaw = (const float*)d_in[22];
    const float* Ww2   = (const float*)d_in[23];
    const float* bw2   = (const float*)d_in[24];

    int n = in_sizes[1] / 3;

    int smA = A_FLOATS * (int)sizeof(float);
    int smB = B_FLOATS * (int)sizeof(float);
    cudaFuncSetAttribute(qkv_kernel,  cudaFuncAttributeMaxDynamicSharedMemorySize, smA);
    cudaFuncSetAttribute(attn_kernel, cudaFuncAttributeMaxDynamicSharedMemorySize, smB);

    int blocksA = (n + 63) / 64;
    qkv_kernel<<<blocksA, 192, smA>>>(feat, coord, Wq, bq, gq, betaq,
                                      Wk, bk, gk, betak, Wv, bv, Ww1, gw, n);

    int occ = 0;
    cudaOccupancyMaxActiveBlocksPerMultiprocessor(&occ, attn_kernel, 384, smB);
    if (occ < 1) occ = 1;
    int nsm = 0;
    cudaDeviceGetAttribute(&nsm, cudaDevAttrMultiProcessorCount, 0);
    if (nsm <= 0) nsm = 148;
    int blocksB = occ * nsm;
    int quads = (n + 3) / 4;
    if (blocksB > quads) blocksB = quads;

    attn_kernel<<<blocksB, 384, smB>>>(ref,
                                       Wp1, bp1, gp, betap, Wp2, bp2,
                                       Ww1, bw1, gw, betaw, Ww2, bw2,
                                       (float*)d_out, n);
}

// round 12
// speedup vs baseline: 1.0157x; 1.0157x over previous
#include <cuda_runtime.h>

#define NMAX 50000
#define C 96

__device__ float g_v[NMAX * C];
__device__ float g_Q1[NMAX * 8];
__device__ float g_K1[NMAX * 8];
__device__ float4 g_c4[NMAX];

// ---- f32x2 packed-math helpers (sm_103a) ----
typedef unsigned long long ull;
#define FFMA2(d, a, b, c) \
    asm("fma.rn.f32x2 %0, %1, %2, %3;" : "=l"(d) : "l"(a), "l"(b), "l"(c))
#define LDS2X64(a, b, addr) \
    asm volatile("ld.shared.v2.u64 {%0, %1}, [%2];" : "=l"(a), "=l"(b) : "r"(addr))
#define DUP2(d, f) \
    asm("mov.b64 %0, {%1, %1};" : "=l"(d) : "r"(__float_as_uint(f)))
#define UNPK(lo, hi, p) do { unsigned _ul, _uh; \
    asm("mov.b64 {%0, %1}, %2;" : "=r"(_ul), "=r"(_uh) : "l"(p)); \
    lo = __uint_as_float(_ul); hi = __uint_as_float(_uh); } while (0)
#define LANE_BAR(id) \
    asm volatile("bar.sync %0, 96;" :: "r"(id) : "memory")

__device__ __forceinline__ unsigned smaddr(const void* p) {
    unsigned r;
    asm("{.reg .u64 t; cvta.to.shared.u64 t, %1; cvt.u32.u64 %0, t;}"
        : "=r"(r) : "l"(p));
    return r;
}

// ---------------------------------------------------------------------------
// Kernel A (unchanged proven R9/R10): v, Q1, K1; rows aliases Ws.
// ---------------------------------------------------------------------------
#define A_FEATT 0            // 96*68 = 6528
#define A_WS    6528         // 96*96 = 9216  (rows[64][100]=6400 aliases here)
#define A_W1T   15744        // Ww1fT[6][100] = 600
#define A_FLOATS 16344

__global__ __launch_bounds__(192) void qkv_kernel(
    const float* __restrict__ feat, const float* __restrict__ coord,
    const float* __restrict__ Wq, const float* __restrict__ bq,
    const float* __restrict__ gq, const float* __restrict__ betaq,
    const float* __restrict__ Wk, const float* __restrict__ bk,
    const float* __restrict__ gk, const float* __restrict__ betak,
    const float* __restrict__ Wv, const float* __restrict__ bv,
    const float* __restrict__ Ww1, const float* __restrict__ gw,
    int n)
{
    extern __shared__ float sm[];
    float* featT = sm + A_FEATT;
    float* Ws    = sm + A_WS;
    float* rows  = sm + A_WS;    // ALIAS
    float* Ww1fT = sm + A_W1T;
    const int tid = threadIdx.x;
    const int tx = tid % 24, ty = tid / 24;
    const int base = blockIdx.x * 64;

    if (tid < 64) {
        int row = base + tid;
        if (row < n) {
            float4 c;
            c.x = coord[row * 3 + 0];
            c.y = coord[row * 3 + 1];
            c.z = coord[row * 3 + 2];
            c.w = 0.f;
            g_c4[row] = c;
        }
    }

    for (int i = tid; i < 64 * 96; i += 192) {
        int r = i / 96, j = i % 96;
        featT[j * 68 + r] = (base + r < n) ? feat[(base + r) * 96 + j] : 0.f;
    }
    for (int i = tid; i < 600; i += 192) {
        int g = i / 100, c = i % 100;
        Ww1fT[i] = (c < 96) ? Ww1[c * 6 + g] * (gw[g] * rsqrtf(1.00001f)) : 0.f;
    }

    const unsigned fbase  = smaddr(featT) + 8 * ty * 4;
    const unsigned rows_b = smaddr(rows);
    const unsigned w1t_b  = smaddr(Ww1fT);

    for (int m = 0; m < 3; m++) {
        const float* W = (m == 0) ? Wq : ((m == 1) ? Wk : Wv);
        __syncthreads();
        for (int i = tid; i < 96 * 96; i += 192) Ws[i] = W[i];
        __syncthreads();

        ull acc2[4][4];
        #pragma unroll
        for (int p = 0; p < 4; p++)
            #pragma unroll
            for (int b = 0; b < 4; b++) acc2[p][b] = 0ULL;

        unsigned fa = fbase;
        #pragma unroll 4
        for (int j = 0; j < 96; j++) {
            ull f01, f23, f45, f67;
            LDS2X64(f01, f23, fa);
            LDS2X64(f45, f67, fa + 16);
            fa += 272;
            float4 w4 = *(const float4*)&Ws[j * 96 + 4 * tx];
            ull wd0, wd1, wd2, wd3;
            DUP2(wd0, w4.x); DUP2(wd1, w4.y); DUP2(wd2, w4.z); DUP2(wd3, w4.w);
            FFMA2(acc2[0][0], f01, wd0, acc2[0][0]);
            FFMA2(acc2[0][1], f01, wd1, acc2[0][1]);
            FFMA2(acc2[0][2], f01, wd2, acc2[0][2]);
            FFMA2(acc2[0][3], f01, wd3, acc2[0][3]);
            FFMA2(acc2[1][0], f23, wd0, acc2[1][0]);
            FFMA2(acc2[1][1], f23, wd1, acc2[1][1]);
            FFMA2(acc2[1][2], f23, wd2, acc2[1][2]);
            FFMA2(acc2[1][3], f23, wd3, acc2[1][3]);
            FFMA2(acc2[2][0], f45, wd0, acc2[2][0]);
            FFMA2(acc2[2][1], f45, wd1, acc2[2][1]);
            FFMA2(acc2[2][2], f45, wd2, acc2[2][2]);
            FFMA2(acc2[2][3], f45, wd3, acc2[2][3]);
            FFMA2(acc2[3][0], f67, wd0, acc2[3][0]);
            FFMA2(acc2[3][1], f67, wd1, acc2[3][1]);
            FFMA2(acc2[3][2], f67, wd2, acc2[3][2]);
            FFMA2(acc2[3][3], f67, wd3, acc2[3][3]);
        }

        float acc[8][4];
        #pragma unroll
        for (int p = 0; p < 4; p++)
            #pragma unroll
            for (int b = 0; b < 4; b++)
                UNPK(acc[2 * p][b], acc[2 * p + 1][b], acc2[p][b]);

        if (m == 2) {
            int c = 4 * tx;
            float4 bb = *(const float4*)&bv[c];
            #pragma unroll
            for (int a = 0; a < 8; a++) {
                int row = base + 8 * ty + a;
                if (row < n) {
                    float4 o = {acc[a][0] + bb.x, acc[a][1] + bb.y,
                                acc[a][2] + bb.z, acc[a][3] + bb.w};
                    *(float4*)&g_v[row * 96 + c] = o;
                }
            }
        } else {
            int c = 4 * tx;
            const float* bsrc = (m == 0) ? bq : bk;
            const float* gsrc = (m == 0) ? gq : gk;
            const float* besrc = (m == 0) ? betaq : betak;
            float4 bb = *(const float4*)&bsrc[c];
            float4 gg = *(const float4*)&gsrc[c];
            float4 be = *(const float4*)&besrc[c];
            float rs = rsqrtf(1.00001f);
            float aa[4] = {gg.x * rs, gg.y * rs, gg.z * rs, gg.w * rs};
            float bba[4] = {bb.x, bb.y, bb.z, bb.w};
            float bea[4] = {be.x, be.y, be.z, be.w};
            __syncthreads();
            #pragma unroll
            for (int a = 0; a < 8; a++) {
                float4 o;
                o.x = fmaxf((acc[a][0] + bba[0]) * aa[0] + bea[0], 0.f);
                o.y = fmaxf((acc[a][1] + bba[1]) * aa[1] + bea[1], 0.f);
                o.z = fmaxf((acc[a][2] + bba[2]) * aa[2] + bea[2], 0.f);
                o.w = fmaxf((acc[a][3] + bba[3]) * aa[3] + bea[3], 0.f);
                *(float4*)&rows[(8 * ty + a) * 100 + c] = o;
            }
            __syncthreads();
            float* dst = (m == 0) ? g_Q1 : g_K1;
            #pragma unroll
            for (int rr = 0; rr < 2; rr++) {
                int i = rr * 192 + tid;
                int r = i / 6, g = i % 6;
                ull a01 = 0ULL, a23 = 0ULL;
                unsigned rb = rows_b + r * 400;
                unsigned wb = w1t_b + g * 400;
                #pragma unroll
                for (int t = 0; t < 24; t++) {
                    ull r01, r23, w01, w23;
                    LDS2X64(r01, r23, rb); rb += 16;
                    LDS2X64(w01, w23, wb); wb += 16;
                    FFMA2(a01, r01, w01, a01);
                    FFMA2(a23, r23, w23, a23);
                }
                float l0, l1v, l2v, l3;
                UNPK(l0, l1v, a01); UNPK(l2v, l3, a23);
                if (base + r < n)
                    dst[(base + r) * 8 + g] = (l0 + l2v) + (l1v + l3);
            }
        }
    }
}

// ---------------------------------------------------------------------------
// Kernel B: fused attention (R10 base + de-padded pos + hoisted Wp1f).
// 384 threads = 4 point-lanes x 96; pipelined ph1; per-lane named barriers.
// ---------------------------------------------------------------------------
#define SH_WP2T 0        // [96][100]
#define SH_FT   9600     // [6][100]
#define SH_WP1F 10200    // [96][4]
#define SH_BP2  10584    // 96
#define SH_WW2  10680    // 40
#define SH_BW2  10720    // 8
#define SH_CB   10728    // 8
#define SH_W1F  10736    // 576
#define SH_PART 11312    // [16][96]
#define SH_LANE 12848
// per-lane (floats)
#define L_HT   0         // hT[16][100]; aliased as At[6][100] later
#define L_PB   1600      // Pb[3][16][8] = 384
#define L_WH   1984      // [16][8]
#define L_LW   2112      // [16][8]
#define L_POS  2240      // 2 x (posx16,posy16,posz16) in 64-float slots = 128
#define L_MSK  2368      // 2 x 16 = 32
#define L_SW   2400      // 8
#define L_K1S  2408      // 2 x [16][8] = 256
#define L_IDX  2664      // 2 x 16 ints = 32
#define LZ     2720
#define B_FLOATS (SH_LANE + 4 * LZ)   // 23728 floats = 94.9 KB

__global__ __launch_bounds__(384, 2) void attn_kernel(
    const int* __restrict__ refidx,
    const float* __restrict__ Wp1, const float* __restrict__ bp1,
    const float* __restrict__ gp,  const float* __restrict__ betap,
    const float* __restrict__ Wp2, const float* __restrict__ bp2,
    const float* __restrict__ Ww1, const float* __restrict__ bw1,
    const float* __restrict__ gw,  const float* __restrict__ betaw,
    const float* __restrict__ Ww2, const float* __restrict__ bw2,
    float* __restrict__ out, int n)
{
    extern __shared__ float sm[];
    float* Wp2T  = sm + SH_WP2T;
    float* Fts   = sm + SH_FT;
    float* Wp1f  = sm + SH_WP1F;
    float* bp2s  = sm + SH_BP2;
    float* Ww2s  = sm + SH_WW2;
    float* bw2s  = sm + SH_BW2;
    float* CBs   = sm + SH_CB;
    float* Ww1fs = sm + SH_W1F;
    float* part  = sm + SH_PART;

    const int tid  = threadIdx.x;
    const int pp   = tid / 96;
    const int jr   = tid % 96;
    const int wl   = jr / 32;
    const int lane = tid & 31;
    const int sL   = jr & 15, gL = jr >> 4;
    const int barid = 1 + pp;

    float* lzone = sm + SH_LANE + pp * LZ;
    float* hT    = lzone + L_HT;
    float* At    = lzone + L_HT;
    float* Pb    = lzone + L_PB;
    float* whes  = lzone + L_WH;
    float* l2w   = lzone + L_LW;
    float* masks = lzone + L_MSK;
    float* swv   = lzone + L_SW;
    float* K1s   = lzone + L_K1S;
    int*   idxp  = (int*)(lzone + L_IDX);

    const unsigned sb     = smaddr(sm);
    const unsigned ht_b   = sb + 4 * (SH_LANE + pp * LZ + L_HT);
    const unsigned lw_b   = sb + 4 * (SH_LANE + pp * LZ + L_LW);
    const unsigned ft_b   = sb + 4 * SH_FT;
    const unsigned wp2_b  = sb + 4 * SH_WP2T;

    // ---- one-time staging ----
    for (int i = tid; i < 9216; i += 384)
        Wp2T[(i % 96) * 100 + i / 96] = Wp2[i];
    if (tid < 96) {
        float ap = gp[tid] * rsqrtf(1.00001f);
        Wp1f[tid * 4 + 0] = Wp1[tid]       * ap;
        Wp1f[tid * 4 + 1] = Wp1[96 + tid]  * ap;
        Wp1f[tid * 4 + 2] = Wp1[192 + tid] * ap;
        Wp1f[tid * 4 + 3] = bp1[tid] * ap + betap[tid];
        bp2s[tid] = bp2[tid];
    }
    if (tid < 36) Ww2s[tid] = Ww2[tid];
    if (tid < 6)  bw2s[tid] = bw2[tid];
    for (int i = tid; i < 576; i += 384) {
        int g = i % 6;
        Ww1fs[i] = Ww1[i] * (gw[g] * rsqrtf(1.00001f));
    }
    __syncthreads();
    for (int i = tid; i < 576; i += 384) {
        int j = i / 6, g = i % 6;
        float f = 0.f;
        #pragma unroll 8
        for (int c = 0; c < 96; c++) f += Wp2T[c * 100 + j] * Ww1fs[c * 6 + g];
        Fts[g * 100 + j] = f;
    }
    if (tid < 6) {
        float aw = gw[tid] * rsqrtf(1.00001f);
        float cb = bw1[tid] * aw + betaw[tid];
        for (int c = 0; c < 96; c++) cb += bp2s[c] * Ww1fs[c * 6 + tid];
        CBs[tid] = cb;
    }
    __syncthreads();

    // loop-invariant: this thread's folded Wp1 row (hoisted out of main loop)
    const float4 wp = *(const float4*)&Wp1f[jr * 4];

    // ---- ph1 loader (warp0: pos/mask/idx; warp1: K1), buffer b ----
    auto load_ph1 = [&](int nn2, int b) {
        if (nn2 < n && lane < 16) {
            if (wl == 0) {
                int raw = refidx[nn2 * 16 + lane];
                int vv = raw + 1;
                masks[b * 16 + lane] = (vv > 0) ? 1.f : ((vv < 0) ? -1.f : 0.f);
                int idx = (raw < 0) ? raw + n : raw;
                idxp[b * 16 + lane] = idx;
                float4 c0 = g_c4[nn2];
                float4 cn = g_c4[idx];
                float* posb = lzone + L_POS + b * 64;
                posb[lane]      = cn.x - c0.x;
                posb[16 + lane] = cn.y - c0.y;
                posb[32 + lane] = cn.z - c0.z;
            } else if (wl == 1) {
                int raw = refidx[nn2 * 16 + lane];
                int idx = (raw < 0) ? raw + n : raw;
                float4 ka = *(const float4*)&g_K1[idx * 8];
                float4 kb = *(const float4*)&g_K1[idx * 8 + 4];
                *(float4*)&K1s[b * 128 + lane * 8] = ka;
                *(float4*)&K1s[b * 128 + lane * 8 + 4] = kb;
            }
        }
    };

    load_ph1(blockIdx.x * 4 + pp, 0);

    int par = 0;
    for (int it = blockIdx.x; it * 4 < n; it += gridDim.x) {
        int nn = it * 4 + pp;
        bool act = (nn < n);

        LANE_BAR(barid);   // ph1[par] visible to this lane

        // ---- ph2: h[s] per thread-j (scalar pos reads, hoisted wp) ----
        float h[16];
        if (act) {
            const float* posb = lzone + L_POS + par * 64;
            #pragma unroll
            for (int s = 0; s < 16; s++) {
                float px = posb[s], py = posb[16 + s], pz = posb[32 + s];
                float hv = fmaxf(wp.w + px * wp.x + py * wp.y + pz * wp.z, 0.f);
                h[s] = hv;
                hT[s * 100 + jr] = hv;
            }
        }
        __syncwarp();   // ph3 reads only this warp's hT columns

        // ---- ph3: l1 partials, j-split across warps ----
        if (act) {
            int s = lane & 15, gt = lane >> 4;
            int j0 = 32 * wl;
            ull ag0 = 0ULL, ag1 = 0ULL, ag2 = 0ULL;
            unsigned hb  = ht_b + (s * 100 + j0) * 4;
            unsigned f0b = ft_b + ((gt * 3 + 0) * 100 + j0) * 4;
            unsigned f1b = f0b + 400;
            unsigned f2b = f1b + 400;
            #pragma unroll
            for (int t = 0; t < 8; t++) {
                ull h01, h23, f01, f23;
                LDS2X64(h01, h23, hb); hb += 16;
                LDS2X64(f01, f23, f0b); f0b += 16;
                FFMA2(ag0, h01, f01, ag0);
                FFMA2(ag0, h23, f23, ag0);
                LDS2X64(f01, f23, f1b); f1b += 16;
                FFMA2(ag1, h01, f01, ag1);
                FFMA2(ag1, h23, f23, ag1);
                LDS2X64(f01, f23, f2b); f2b += 16;
                FFMA2(ag2, h01, f01, ag2);
                FFMA2(ag2, h23, f23, ag2);
            }
            float x0, x1;
            float* pb = Pb + wl * 128 + s * 8 + gt * 4;
            UNPK(x0, x1, ag0); pb[0] = x0 + x1;
            UNPK(x0, x1, ag1); pb[1] = x0 + x1;
            UNPK(x0, x1, ag2); pb[2] = x0 + x1;
        }
        LANE_BAR(barid);

        // ---- ph3b: combine partials + K1/Q1, wh = relu(l1) ----
        if (act) {
            int slot = gL + (gL >= 3 ? 1 : 0);
            float l1 = CBs[gL] + K1s[par * 128 + sL * 8 + gL] - g_Q1[nn * 8 + gL]
                     + Pb[0 * 128 + sL * 8 + slot]
                     + Pb[1 * 128 + sL * 8 + slot]
                     + Pb[2 * 128 + sL * 8 + slot];
            whes[sL * 8 + gL] = fmaxf(l1, 0.f);
        }
        LANE_BAR(barid);

        // ---- ph456: l2, 16-lane softmax, masked weights ----
        if (act) {
            float l2 = bw2s[gL];
            #pragma unroll
            for (int gg = 0; gg < 6; gg++)
                l2 += whes[sL * 8 + gg] * Ww2s[gg * 6 + gL];
            float mx = l2;
            #pragma unroll
            for (int off = 8; off >= 1; off >>= 1)
                mx = fmaxf(mx, __shfl_xor_sync(0xffffffffu, mx, off, 16));
            float e  = __expf(l2 - mx);
            float em = e * masks[par * 16 + sL];
            float ss = e, ms = em;
            #pragma unroll
            for (int off = 8; off >= 1; off >>= 1) {
                ss += __shfl_xor_sync(0xffffffffu, ss, off, 16);
                ms += __shfl_xor_sync(0xffffffffu, ms, off, 16);
            }
            l2w[sL * 8 + gL] = em / ss;
            if (sL == 0) swv[gL] = ms / ss;
        }
        LANE_BAR(barid);

        // ---- prefetch next iteration's ph1 (overlaps ph7/8) ----
        load_ph1((it + gridDim.x) * 4 + pp, par ^ 1);

        // ---- ph7: A[j,g] = sum_s h[s,j] w[s,g]  (f32x2) ----
        if (act) {
            ull A01 = 0ULL, A23 = 0ULL, A45 = 0ULL;
            unsigned lb = lw_b;
            #pragma unroll
            for (int s = 0; s < 16; s++) {
                ull w01, w23, w45, w67;
                LDS2X64(w01, w23, lb);
                LDS2X64(w45, w67, lb + 16);
                lb += 32;
                ull hd; DUP2(hd, h[s]);
                FFMA2(A01, hd, w01, A01);
                FFMA2(A23, hd, w23, A23);
                FFMA2(A45, hd, w45, A45);
            }
            float A0, A1, A2, A3, A4, A5;
            UNPK(A0, A1, A01);
            UNPK(A2, A3, A23);
            UNPK(A4, A5, A45);
            At[0 * 100 + jr] = A0; At[1 * 100 + jr] = A1; At[2 * 100 + jr] = A2;
            At[3 * 100 + jr] = A3; At[4 * 100 + jr] = A4; At[5 * 100 + jr] = A5;
        }
        __syncthreads();   // cross-lane: ph8a reads all lanes' At

        // ---- ph8a: quartered Wp2^T @ A across 4 points (f32x2) ----
        {
            int c = jr, g = jr >> 4, j0 = pp * 24;
            ull pt2[4] = {0ULL, 0ULL, 0ULL, 0ULL};
            unsigned wb = wp2_b + (c * 100 + j0) * 4;
            unsigned ab0 = sb + 4 * (SH_LANE + 0 * LZ + L_HT) + (g * 100 + j0) * 4;
            unsigned ab1 = sb + 4 * (SH_LANE + 1 * LZ + L_HT) + (g * 100 + j0) * 4;
            unsigned ab2 = sb + 4 * (SH_LANE + 2 * LZ + L_HT) + (g * 100 + j0) * 4;
            unsigned ab3 = sb + 4 * (SH_LANE + 3 * LZ + L_HT) + (g * 100 + j0) * 4;
            #pragma unroll
            for (int t = 0; t < 6; t++) {
                ull w01, w23, a01, a23;
                LDS2X64(w01, w23, wb); wb += 16;
                LDS2X64(a01, a23, ab0); ab0 += 16;
                FFMA2(pt2[0], w01, a01, pt2[0]);
                FFMA2(pt2[0], w23, a23, pt2[0]);
                LDS2X64(a01, a23, ab1); ab1 += 16;
                FFMA2(pt2[1], w01, a01, pt2[1]);
                FFMA2(pt2[1], w23, a23, pt2[1]);
                LDS2X64(a01, a23, ab2); ab2 += 16;
                FFMA2(pt2[2], w01, a01, pt2[2]);
                FFMA2(pt2[2], w23, a23, pt2[2]);
                LDS2X64(a01, a23, ab3); ab3 += 16;
                FFMA2(pt2[3], w01, a01, pt2[3]);
                FFMA2(pt2[3], w23, a23, pt2[3]);
            }
            #pragma unroll
            for (int p = 0; p < 4; p++) {
                float lo, hi;
                UNPK(lo, hi, pt2[p]);
                part[(pp * 4 + p) * 96 + c] = lo + hi;
            }
        }
        __syncthreads();   // cross-lane: ph8b reads all lanes' part

        // ---- ph8b: combine quarters + v-gather term, store out ----
        if (act) {
            int c = jr, g = jr >> 4;
            const int* idq = (const int*)(lzone + L_IDX) + par * 16;
            float o = bp2s[c] * swv[g];
            o += part[(0 * 4 + pp) * 96 + c] + part[(1 * 4 + pp) * 96 + c]
               + part[(2 * 4 + pp) * 96 + c] + part[(3 * 4 + pp) * 96 + c];
            float vv[16];
            #pragma unroll
            for (int s = 0; s < 16; s++)
                vv[s] = g_v[idq[s] * 96 + c];
            #pragma unroll
            for (int s = 0; s < 16; s++)
                o += vv[s] * l2w[s * 8 + g];
            out[nn * 96 + c] = o;
        }
        par ^= 1;
    }
}

extern "C" void kernel_launch(void* const* d_in, const int* in_sizes, int n_in,
                              void* d_out, int out_size) {
    const float* feat  = (const float*)d_in[0];
    const float* coord = (const float*)d_in[1];
    const int*   ref   = (const int*)d_in[2];
    const float* Wq    = (const float*)d_in[3];
    const float* bq    = (const float*)d_in[4];
    const float* gq    = (const float*)d_in[5];
    const float* betaq = (const float*)d_in[6];
    const float* Wk    = (const float*)d_in[7];
    const float* bk    = (const float*)d_in[8];
    const float* gk    = (const float*)d_in[9];
    const float* betak = (const float*)d_in[10];
    const float* Wv    = (const float*)d_in[11];
    const float* bv    = (const float*)d_in[12];
    const float* Wp1   = (const float*)d_in[13];
    const float* bp1   = (const float*)d_in[14];
    const float* gp    = (const float*)d_in[15];
    const float* betap = (const float*)d_in[16];
    const float* Wp2   = (const float*)d_in[17];
    const float* bp2   = (const float*)d_in[18];
    const float* Ww1   = (const float*)d_in[19];
    const float* bw1   = (const float*)d_in[20];
    const float* gw    = (const float*)d_in[21];
    const float* betaw = (const float*)d_in[22];
    const float* Ww2   = (const float*)d_in[23];
    const float* bw2   = (const float*)d_in[24];

    int n = in_sizes[1] / 3;

    int smA = A_FLOATS * (int)sizeof(float);
    int smB = B_FLOATS * (int)sizeof(float);
    cudaFuncSetAttribute(qkv_kernel,  cudaFuncAttributeMaxDynamicSharedMemorySize, smA);
    cudaFuncSetAttribute(attn_kernel, cudaFuncAttributeMaxDynamicSharedMemorySize, smB);

    int blocksA = (n + 63) / 64;
    qkv_kernel<<<blocksA, 192, smA>>>(feat, coord, Wq, bq, gq, betaq,
                                      Wk, bk, gk, betak, Wv, bv, Ww1, gw, n);

    int occ = 0;
    cudaOccupancyMaxActiveBlocksPerMultiprocessor(&occ, attn_kernel, 384, smB);
    if (occ < 1) occ = 1;
    int nsm = 0;
    cudaDeviceGetAttribute(&nsm, cudaDevAttrMultiProcessorCount, 0);
    if (nsm <= 0) nsm = 148;
    int blocksB = occ * nsm;
    int quads = (n + 3) / 4;
    if (blocksB > quads) blocksB = quads;

    attn_kernel<<<blocksB, 384, smB>>>(ref,
                                       Wp1, bp1, gp, betap, Wp2, bp2,
                                       Ww1, bw1, gw, betaw, Ww2, bw2,
                                       (float*)d_out, n);
}

// round 13
// speedup vs baseline: 1.0170x; 1.0012x over previous
#include <cuda_runtime.h>

#define NMAX 50000
#define C 96

__device__ float g_v[NMAX * C];
__device__ float g_Q1[NMAX * 8];
__device__ float g_K1[NMAX * 8];
__device__ float4 g_c4[NMAX];

// ---- f32x2 packed-math helpers (sm_103a) ----
typedef unsigned long long ull;
#define FFMA2(d, a, b, c) \
    asm("fma.rn.f32x2 %0, %1, %2, %3;" : "=l"(d) : "l"(a), "l"(b), "l"(c))
#define LDS2X64(a, b, addr) \
    asm volatile("ld.shared.v2.u64 {%0, %1}, [%2];" : "=l"(a), "=l"(b) : "r"(addr))
#define DUP2(d, f) \
    asm("mov.b64 %0, {%1, %1};" : "=l"(d) : "r"(__float_as_uint(f)))
#define UNPK(lo, hi, p) do { unsigned _ul, _uh; \
    asm("mov.b64 {%0, %1}, %2;" : "=r"(_ul), "=r"(_uh) : "l"(p)); \
    lo = __uint_as_float(_ul); hi = __uint_as_float(_uh); } while (0)
#define LANE_BAR(id) \
    asm volatile("bar.sync %0, 96;" :: "r"(id) : "memory")

__device__ __forceinline__ unsigned smaddr(const void* p) {
    unsigned r;
    asm("{.reg .u64 t; cvta.to.shared.u64 t, %1; cvt.u32.u64 %0, t;}"
        : "=r"(r) : "l"(p));
    return r;
}

// ---------------------------------------------------------------------------
// Kernel A (unchanged proven): v, Q1, K1; rows aliases Ws.
// ---------------------------------------------------------------------------
#define A_FEATT 0            // 96*68 = 6528
#define A_WS    6528         // 96*96 = 9216  (rows[64][100]=6400 aliases here)
#define A_W1T   15744        // Ww1fT[6][100] = 600
#define A_FLOATS 16344

__global__ __launch_bounds__(192) void qkv_kernel(
    const float* __restrict__ feat, const float* __restrict__ coord,
    const float* __restrict__ Wq, const float* __restrict__ bq,
    const float* __restrict__ gq, const float* __restrict__ betaq,
    const float* __restrict__ Wk, const float* __restrict__ bk,
    const float* __restrict__ gk, const float* __restrict__ betak,
    const float* __restrict__ Wv, const float* __restrict__ bv,
    const float* __restrict__ Ww1, const float* __restrict__ gw,
    int n)
{
    extern __shared__ float sm[];
    float* featT = sm + A_FEATT;
    float* Ws    = sm + A_WS;
    float* rows  = sm + A_WS;    // ALIAS
    float* Ww1fT = sm + A_W1T;
    const int tid = threadIdx.x;
    const int tx = tid % 24, ty = tid / 24;
    const int base = blockIdx.x * 64;

    if (tid < 64) {
        int row = base + tid;
        if (row < n) {
            float4 c;
            c.x = coord[row * 3 + 0];
            c.y = coord[row * 3 + 1];
            c.z = coord[row * 3 + 2];
            c.w = 0.f;
            g_c4[row] = c;
        }
    }

    for (int i = tid; i < 64 * 96; i += 192) {
        int r = i / 96, j = i % 96;
        featT[j * 68 + r] = (base + r < n) ? feat[(base + r) * 96 + j] : 0.f;
    }
    for (int i = tid; i < 600; i += 192) {
        int g = i / 100, c = i % 100;
        Ww1fT[i] = (c < 96) ? Ww1[c * 6 + g] * (gw[g] * rsqrtf(1.00001f)) : 0.f;
    }

    const unsigned fbase  = smaddr(featT) + 8 * ty * 4;
    const unsigned rows_b = smaddr(rows);
    const unsigned w1t_b  = smaddr(Ww1fT);

    for (int m = 0; m < 3; m++) {
        const float* W = (m == 0) ? Wq : ((m == 1) ? Wk : Wv);
        __syncthreads();
        for (int i = tid; i < 96 * 96; i += 192) Ws[i] = W[i];
        __syncthreads();

        ull acc2[4][4];
        #pragma unroll
        for (int p = 0; p < 4; p++)
            #pragma unroll
            for (int b = 0; b < 4; b++) acc2[p][b] = 0ULL;

        unsigned fa = fbase;
        #pragma unroll 4
        for (int j = 0; j < 96; j++) {
            ull f01, f23, f45, f67;
            LDS2X64(f01, f23, fa);
            LDS2X64(f45, f67, fa + 16);
            fa += 272;
            float4 w4 = *(const float4*)&Ws[j * 96 + 4 * tx];
            ull wd0, wd1, wd2, wd3;
            DUP2(wd0, w4.x); DUP2(wd1, w4.y); DUP2(wd2, w4.z); DUP2(wd3, w4.w);
            FFMA2(acc2[0][0], f01, wd0, acc2[0][0]);
            FFMA2(acc2[0][1], f01, wd1, acc2[0][1]);
            FFMA2(acc2[0][2], f01, wd2, acc2[0][2]);
            FFMA2(acc2[0][3], f01, wd3, acc2[0][3]);
            FFMA2(acc2[1][0], f23, wd0, acc2[1][0]);
            FFMA2(acc2[1][1], f23, wd1, acc2[1][1]);
            FFMA2(acc2[1][2], f23, wd2, acc2[1][2]);
            FFMA2(acc2[1][3], f23, wd3, acc2[1][3]);
            FFMA2(acc2[2][0], f45, wd0, acc2[2][0]);
            FFMA2(acc2[2][1], f45, wd1, acc2[2][1]);
            FFMA2(acc2[2][2], f45, wd2, acc2[2][2]);
            FFMA2(acc2[2][3], f45, wd3, acc2[2][3]);
            FFMA2(acc2[3][0], f67, wd0, acc2[3][0]);
            FFMA2(acc2[3][1], f67, wd1, acc2[3][1]);
            FFMA2(acc2[3][2], f67, wd2, acc2[3][2]);
            FFMA2(acc2[3][3], f67, wd3, acc2[3][3]);
        }

        float acc[8][4];
        #pragma unroll
        for (int p = 0; p < 4; p++)
            #pragma unroll
            for (int b = 0; b < 4; b++)
                UNPK(acc[2 * p][b], acc[2 * p + 1][b], acc2[p][b]);

        if (m == 2) {
            int c = 4 * tx;
            float4 bb = *(const float4*)&bv[c];
            #pragma unroll
            for (int a = 0; a < 8; a++) {
                int row = base + 8 * ty + a;
                if (row < n) {
                    float4 o = {acc[a][0] + bb.x, acc[a][1] + bb.y,
                                acc[a][2] + bb.z, acc[a][3] + bb.w};
                    *(float4*)&g_v[row * 96 + c] = o;
                }
            }
        } else {
            int c = 4 * tx;
            const float* bsrc = (m == 0) ? bq : bk;
            const float* gsrc = (m == 0) ? gq : gk;
            const float* besrc = (m == 0) ? betaq : betak;
            float4 bb = *(const float4*)&bsrc[c];
            float4 gg = *(const float4*)&gsrc[c];
            float4 be = *(const float4*)&besrc[c];
            float rs = rsqrtf(1.00001f);
            float aa[4] = {gg.x * rs, gg.y * rs, gg.z * rs, gg.w * rs};
            float bba[4] = {bb.x, bb.y, bb.z, bb.w};
            float bea[4] = {be.x, be.y, be.z, be.w};
            __syncthreads();
            #pragma unroll
            for (int a = 0; a < 8; a++) {
                float4 o;
                o.x = fmaxf((acc[a][0] + bba[0]) * aa[0] + bea[0], 0.f);
                o.y = fmaxf((acc[a][1] + bba[1]) * aa[1] + bea[1], 0.f);
                o.z = fmaxf((acc[a][2] + bba[2]) * aa[2] + bea[2], 0.f);
                o.w = fmaxf((acc[a][3] + bba[3]) * aa[3] + bea[3], 0.f);
                *(float4*)&rows[(8 * ty + a) * 100 + c] = o;
            }
            __syncthreads();
            float* dst = (m == 0) ? g_Q1 : g_K1;
            #pragma unroll
            for (int rr = 0; rr < 2; rr++) {
                int i = rr * 192 + tid;
                int r = i / 6, g = i % 6;
                ull a01 = 0ULL, a23 = 0ULL;
                unsigned rb = rows_b + r * 400;
                unsigned wb = w1t_b + g * 400;
                #pragma unroll
                for (int t = 0; t < 24; t++) {
                    ull r01, r23, w01, w23;
                    LDS2X64(r01, r23, rb); rb += 16;
                    LDS2X64(w01, w23, wb); wb += 16;
                    FFMA2(a01, r01, w01, a01);
                    FFMA2(a23, r23, w23, a23);
                }
                float l0, l1v, l2v, l3;
                UNPK(l0, l1v, a01); UNPK(l2v, l3, a23);
                if (base + r < n)
                    dst[(base + r) * 8 + g] = (l0 + l2v) + (l1v + l3);
            }
        }
    }
}

// ---------------------------------------------------------------------------
// Kernel B: fused attention (R10 base; ph8a retiled to c-pair x j-octant).
// ---------------------------------------------------------------------------
#define SH_WP2T 0        // [96][100]
#define SH_FT   9600     // [6][100]
#define SH_WP1F 10200    // [96][4]
#define SH_BP2  10584    // 96
#define SH_WW2  10680    // 40
#define SH_BW2  10720    // 8
#define SH_CB   10728    // 8
#define SH_W1F  10736    // 576
#define SH_PART 11312    // [32][96] = 3072
#define SH_LANE 14384
// per-lane (floats)
#define L_HT   0         // hT[16][100]; aliased as At[6][100] later
#define L_PB   1600      // Pb[3][16][8] = 384
#define L_WH   1984      // [16][8]
#define L_LW   2112      // [16][8]
#define L_POS  2240      // 2 x [16][4]
#define L_MSK  2368      // 2 x 16
#define L_SW   2400      // 8
#define L_K1S  2408      // 2 x [16][8]
#define L_IDX  2664      // 2 x 16 ints
#define LZ     2720
#define B_FLOATS (SH_LANE + 4 * LZ)   // 25264 floats = 101056 B

__global__ __launch_bounds__(384, 2) void attn_kernel(
    const int* __restrict__ refidx,
    const float* __restrict__ Wp1, const float* __restrict__ bp1,
    const float* __restrict__ gp,  const float* __restrict__ betap,
    const float* __restrict__ Wp2, const float* __restrict__ bp2,
    const float* __restrict__ Ww1, const float* __restrict__ bw1,
    const float* __restrict__ gw,  const float* __restrict__ betaw,
    const float* __restrict__ Ww2, const float* __restrict__ bw2,
    float* __restrict__ out, int n)
{
    extern __shared__ float sm[];
    float* Wp2T  = sm + SH_WP2T;
    float* Fts   = sm + SH_FT;
    float* Wp1f  = sm + SH_WP1F;
    float* bp2s  = sm + SH_BP2;
    float* Ww2s  = sm + SH_WW2;
    float* bw2s  = sm + SH_BW2;
    float* CBs   = sm + SH_CB;
    float* Ww1fs = sm + SH_W1F;
    float* part  = sm + SH_PART;

    const int tid  = threadIdx.x;
    const int pp   = tid / 96;
    const int jr   = tid % 96;
    const int wl   = jr / 32;
    const int lane = tid & 31;
    const int sL   = jr & 15, gL = jr >> 4;
    const int barid = 1 + pp;

    float* lzone = sm + SH_LANE + pp * LZ;
    float* hT    = lzone + L_HT;
    float* At    = lzone + L_HT;
    float* Pb    = lzone + L_PB;
    float* whes  = lzone + L_WH;
    float* l2w   = lzone + L_LW;
    float* poss  = lzone + L_POS;
    float* masks = lzone + L_MSK;
    float* swv   = lzone + L_SW;
    float* K1s   = lzone + L_K1S;
    int*   idxp  = (int*)(lzone + L_IDX);

    const unsigned sb     = smaddr(sm);
    const unsigned ht_b   = sb + 4 * (SH_LANE + pp * LZ + L_HT);
    const unsigned lw_b   = sb + 4 * (SH_LANE + pp * LZ + L_LW);
    const unsigned ft_b   = sb + 4 * SH_FT;
    const unsigned wp2_b  = sb + 4 * SH_WP2T;

    // ---- one-time staging ----
    for (int i = tid; i < 9216; i += 384)
        Wp2T[(i % 96) * 100 + i / 96] = Wp2[i];
    if (tid < 96) {
        float ap = gp[tid] * rsqrtf(1.00001f);
        Wp1f[tid * 4 + 0] = Wp1[tid]       * ap;
        Wp1f[tid * 4 + 1] = Wp1[96 + tid]  * ap;
        Wp1f[tid * 4 + 2] = Wp1[192 + tid] * ap;
        Wp1f[tid * 4 + 3] = bp1[tid] * ap + betap[tid];
        bp2s[tid] = bp2[tid];
    }
    if (tid < 36) Ww2s[tid] = Ww2[tid];
    if (tid < 6)  bw2s[tid] = bw2[tid];
    for (int i = tid; i < 576; i += 384) {
        int g = i % 6;
        Ww1fs[i] = Ww1[i] * (gw[g] * rsqrtf(1.00001f));
    }
    __syncthreads();
    for (int i = tid; i < 576; i += 384) {
        int j = i / 6, g = i % 6;
        float f = 0.f;
        #pragma unroll 8
        for (int c = 0; c < 96; c++) f += Wp2T[c * 100 + j] * Ww1fs[c * 6 + g];
        Fts[g * 100 + j] = f;
    }
    if (tid < 6) {
        float aw = gw[tid] * rsqrtf(1.00001f);
        float cb = bw1[tid] * aw + betaw[tid];
        for (int c = 0; c < 96; c++) cb += bp2s[c] * Ww1fs[c * 6 + tid];
        CBs[tid] = cb;
    }
    __syncthreads();

    // ph8a retile roles: c-pair + j-octant
    const int u8  = tid >> 3;        // 0..47 c-pair
    const int oct = tid & 7;         // 0..7  j-octant (12 j's)
    const int c0  = 2 * u8;
    const int g8  = u8 >> 3;
    const int j8  = oct * 12;

    // ---- ph1 loader (warp0: pos/mask/idx; warp1: K1), buffer b ----
    auto load_ph1 = [&](int nn2, int b) {
        if (nn2 < n && lane < 16) {
            if (wl == 0) {
                int raw = refidx[nn2 * 16 + lane];
                int vv = raw + 1;
                masks[b * 16 + lane] = (vv > 0) ? 1.f : ((vv < 0) ? -1.f : 0.f);
                int idx = (raw < 0) ? raw + n : raw;
                idxp[b * 16 + lane] = idx;
                float4 c0v = g_c4[nn2];
                float4 cnv = g_c4[idx];
                poss[b * 64 + lane * 4 + 0] = cnv.x - c0v.x;
                poss[b * 64 + lane * 4 + 1] = cnv.y - c0v.y;
                poss[b * 64 + lane * 4 + 2] = cnv.z - c0v.z;
            } else if (wl == 1) {
                int raw = refidx[nn2 * 16 + lane];
                int idx = (raw < 0) ? raw + n : raw;
                float4 ka = *(const float4*)&g_K1[idx * 8];
                float4 kb = *(const float4*)&g_K1[idx * 8 + 4];
                *(float4*)&K1s[b * 128 + lane * 8] = ka;
                *(float4*)&K1s[b * 128 + lane * 8 + 4] = kb;
            }
        }
    };

    load_ph1(blockIdx.x * 4 + pp, 0);

    int par = 0;
    for (int it = blockIdx.x; it * 4 < n; it += gridDim.x) {
        int nn = it * 4 + pp;
        bool act = (nn < n);

        LANE_BAR(barid);   // ph1[par] visible to this lane

        // ---- ph2: h[s] per thread-j ----
        float h[16];
        if (act) {
            float4 wp = *(const float4*)&Wp1f[jr * 4];
            #pragma unroll
            for (int s = 0; s < 16; s++) {
                float4 p = *(const float4*)&poss[par * 64 + s * 4];
                float hv = fmaxf(wp.w + p.x * wp.x + p.y * wp.y + p.z * wp.z, 0.f);
                h[s] = hv;
                hT[s * 100 + jr] = hv;
            }
        }
        __syncwarp();

        // ---- ph3: l1 partials, j-split across warps ----
        if (act) {
            int s = lane & 15, gt = lane >> 4;
            int j0 = 32 * wl;
            ull ag0 = 0ULL, ag1 = 0ULL, ag2 = 0ULL;
            unsigned hb  = ht_b + (s * 100 + j0) * 4;
            unsigned f0b = ft_b + ((gt * 3 + 0) * 100 + j0) * 4;
            unsigned f1b = f0b + 400;
            unsigned f2b = f1b + 400;
            #pragma unroll
            for (int t = 0; t < 8; t++) {
                ull h01, h23, f01, f23;
                LDS2X64(h01, h23, hb); hb += 16;
                LDS2X64(f01, f23, f0b); f0b += 16;
                FFMA2(ag0, h01, f01, ag0);
                FFMA2(ag0, h23, f23, ag0);
                LDS2X64(f01, f23, f1b); f1b += 16;
                FFMA2(ag1, h01, f01, ag1);
                FFMA2(ag1, h23, f23, ag1);
                LDS2X64(f01, f23, f2b); f2b += 16;
                FFMA2(ag2, h01, f01, ag2);
                FFMA2(ag2, h23, f23, ag2);
            }
            float x0, x1;
            float* pb = Pb + wl * 128 + s * 8 + gt * 4;
            UNPK(x0, x1, ag0); pb[0] = x0 + x1;
            UNPK(x0, x1, ag1); pb[1] = x0 + x1;
            UNPK(x0, x1, ag2); pb[2] = x0 + x1;
        }
        LANE_BAR(barid);

        // ---- ph3b: combine partials + K1/Q1, wh = relu(l1) ----
        if (act) {
            int slot = gL + (gL >= 3 ? 1 : 0);
            float l1 = CBs[gL] + K1s[par * 128 + sL * 8 + gL] - g_Q1[nn * 8 + gL]
                     + Pb[0 * 128 + sL * 8 + slot]
                     + Pb[1 * 128 + sL * 8 + slot]
                     + Pb[2 * 128 + sL * 8 + slot];
            whes[sL * 8 + gL] = fmaxf(l1, 0.f);
        }
        LANE_BAR(barid);

        // ---- ph456: l2, 16-lane softmax, masked weights ----
        if (act) {
            float l2 = bw2s[gL];
            #pragma unroll
            for (int gg = 0; gg < 6; gg++)
                l2 += whes[sL * 8 + gg] * Ww2s[gg * 6 + gL];
            float mx = l2;
            #pragma unroll
            for (int off = 8; off >= 1; off >>= 1)
                mx = fmaxf(mx, __shfl_xor_sync(0xffffffffu, mx, off, 16));
            float e  = __expf(l2 - mx);
            float em = e * masks[par * 16 + sL];
            float ss = e, ms = em;
            #pragma unroll
            for (int off = 8; off >= 1; off >>= 1) {
                ss += __shfl_xor_sync(0xffffffffu, ss, off, 16);
                ms += __shfl_xor_sync(0xffffffffu, ms, off, 16);
            }
            l2w[sL * 8 + gL] = em / ss;
            if (sL == 0) swv[gL] = ms / ss;
        }
        LANE_BAR(barid);

        // ---- prefetch next iteration's ph1 (overlaps ph7/8) ----
        load_ph1((it + gridDim.x) * 4 + pp, par ^ 1);

        // ---- ph7: A[j,g] = sum_s h[s,j] w[s,g]  (f32x2) ----
        if (act) {
            ull A01 = 0ULL, A23 = 0ULL, A45 = 0ULL;
            unsigned lb = lw_b;
            #pragma unroll
            for (int s = 0; s < 16; s++) {
                ull w01, w23, w45, w67;
                LDS2X64(w01, w23, lb);
                LDS2X64(w45, w67, lb + 16);
                lb += 32;
                ull hd; DUP2(hd, h[s]);
                FFMA2(A01, hd, w01, A01);
                FFMA2(A23, hd, w23, A23);
                FFMA2(A45, hd, w45, A45);
            }
            float A0, A1, A2, A3, A4, A5;
            UNPK(A0, A1, A01);
            UNPK(A2, A3, A23);
            UNPK(A4, A5, A45);
            At[0 * 100 + jr] = A0; At[1 * 100 + jr] = A1; At[2 * 100 + jr] = A2;
            At[3 * 100 + jr] = A3; At[4 * 100 + jr] = A4; At[5 * 100 + jr] = A5;
        }
        __syncthreads();   // cross-lane: ph8a reads all lanes' At

        // ---- ph8a: retiled Wp2^T @ A — thread = (c-pair, j-octant), 4 pts.
        //      Per thread: 2 c's x 12 j's x 4 points; balanced w/A reads. ----
        {
            ull acc8[2][4];
            #pragma unroll
            for (int ci = 0; ci < 2; ci++)
                #pragma unroll
                for (int p = 0; p < 4; p++) acc8[ci][p] = 0ULL;

            unsigned w0b = wp2_b + (c0 * 100 + j8) * 4;
            unsigned w1b = w0b + 400;
            unsigned ab[4];
            #pragma unroll
            for (int p = 0; p < 4; p++)
                ab[p] = sb + 4 * (SH_LANE + p * LZ + L_HT) + (g8 * 100 + j8) * 4;

            #pragma unroll
            for (int t = 0; t < 3; t++) {
                ull wa0, wb0, wa1, wb1;
                LDS2X64(wa0, wb0, w0b); w0b += 16;
                LDS2X64(wa1, wb1, w1b); w1b += 16;
                #pragma unroll
                for (int p = 0; p < 4; p++) {
                    ull aa, abv;
                    LDS2X64(aa, abv, ab[p]); ab[p] += 16;
                    FFMA2(acc8[0][p], wa0, aa,  acc8[0][p]);
                    FFMA2(acc8[0][p], wb0, abv, acc8[0][p]);
                    FFMA2(acc8[1][p], wa1, aa,  acc8[1][p]);
                    FFMA2(acc8[1][p], wb1, abv, acc8[1][p]);
                }
            }
            int sc = (c0 + 4 * oct) % 96;   // skewed column (store-conflict fix)
            #pragma unroll
            for (int p = 0; p < 4; p++) {
                float l0, h0, l1, h1;
                UNPK(l0, h0, acc8[0][p]);
                UNPK(l1, h1, acc8[1][p]);
                float2 pr = {l0 + h0, l1 + h1};
                *(float2*)&part[(oct * 4 + p) * 96 + sc] = pr;
            }
        }
        __syncthreads();   // cross-lane: ph8b reads all parts

        // ---- ph8b: combine octants (de-skew) + v-gather term, store out ----
        if (act) {
            int c = jr, g = jr >> 4;
            const int* idq = (const int*)(lzone + L_IDX) + par * 16;
            float o = bp2s[c] * swv[g];
            #pragma unroll
            for (int oc = 0; oc < 8; oc++) {
                int col = c + 4 * oc; if (col >= 96) col -= 96;
                o += part[(oc * 4 + pp) * 96 + col];
            }
            float vv[16];
            #pragma unroll
            for (int s = 0; s < 16; s++)
                vv[s] = g_v[idq[s] * 96 + c];
            #pragma unroll
            for (int s = 0; s < 16; s++)
                o += vv[s] * l2w[s * 8 + g];
            out[nn * 96 + c] = o;
        }
        par ^= 1;
    }
}

extern "C" void kernel_launch(void* const* d_in, const int* in_sizes, int n_in,
                              void* d_out, int out_size) {
    const float* feat  = (const float*)d_in[0];
    const float* coord = (const float*)d_in[1];
    const int*   ref   = (const int*)d_in[2];
    const float* Wq    = (const float*)d_in[3];
    const float* bq    = (const float*)d_in[4];
    const float* gq    = (const float*)d_in[5];
    const float* betaq = (const float*)d_in[6];
    const float* Wk    = (const float*)d_in[7];
    const float* bk    = (const float*)d_in[8];
    const float* gk    = (const float*)d_in[9];
    const float* betak = (const float*)d_in[10];
    const float* Wv    = (const float*)d_in[11];
    const float* bv    = (const float*)d_in[12];
    const float* Wp1   = (const float*)d_in[13];
    const float* bp1   = (const float*)d_in[14];
    const float* gp    = (const float*)d_in[15];
    const float* betap = (const float*)d_in[16];
    const float* Wp2   = (const float*)d_in[17];
    const float* bp2   = (const float*)d_in[18];
    const float* Ww1   = (const float*)d_in[19];
    const float* bw1   = (const float*)d_in[20];
    const float* gw    = (const float*)d_in[21];
    const float* betaw = (const float*)d_in[22];
    const float* Ww2   = (const float*)d_in[23];
    const float* bw2   = (const float*)d_in[24];

    int n = in_sizes[1] / 3;

    int smA = A_FLOATS * (int)sizeof(float);
    int smB = B_FLOATS * (int)sizeof(float);
    cudaFuncSetAttribute(qkv_kernel,  cudaFuncAttributeMaxDynamicSharedMemorySize, smA);
    cudaFuncSetAttribute(attn_kernel, cudaFuncAttributeMaxDynamicSharedMemorySize, smB);

    int blocksA = (n + 63) / 64;
    qkv_kernel<<<blocksA, 192, smA>>>(feat, coord, Wq, bq, gq, betaq,
                                      Wk, bk, gk, betak, Wv, bv, Ww1, gw, n);

    int occ = 0;
    cudaOccupancyMaxActiveBlocksPerMultiprocessor(&occ, attn_kernel, 384, smB);
    if (occ < 1) occ = 1;
    int nsm = 0;
    cudaDeviceGetAttribute(&nsm, cudaDevAttrMultiProcessorCount, 0);
    if (nsm <= 0) nsm = 148;
    int blocksB = occ * nsm;
    int quads = (n + 3) / 4;
    if (blocksB > quads) blocksB = quads;

    attn_kernel<<<blocksB, 384, smB>>>(ref,
                                       Wp1, bp1, gp, betap, Wp2, bp2,
                                       Ww1, bw1, gw, betaw, Ww2, bw2,
                                       (float*)d_out, n);
}

// round 14
// speedup vs baseline: 1.0193x; 1.0023x over previous
#include <cuda_runtime.h>

#define NMAX 50000
#define C 96

__device__ float g_v[NMAX * C];
__device__ float g_Q1[NMAX * 8];
__device__ float g_K1[NMAX * 8];
__device__ float4 g_c4[NMAX];

// ---- f32x2 packed-math helpers (sm_103a) ----
typedef unsigned long long ull;
#define FFMA2(d, a, b, c) \
    asm("fma.rn.f32x2 %0, %1, %2, %3;" : "=l"(d) : "l"(a), "l"(b), "l"(c))
#define LDS2X64(a, b, addr) \
    asm volatile("ld.shared.v2.u64 {%0, %1}, [%2];" : "=l"(a), "=l"(b) : "r"(addr))
#define DUP2(d, f) \
    asm("mov.b64 %0, {%1, %1};" : "=l"(d) : "r"(__float_as_uint(f)))
#define UNPK(lo, hi, p) do { unsigned _ul, _uh; \
    asm("mov.b64 {%0, %1}, %2;" : "=r"(_ul), "=r"(_uh) : "l"(p)); \
    lo = __uint_as_float(_ul); hi = __uint_as_float(_uh); } while (0)
#define LANE_BAR(id) \
    asm volatile("bar.sync %0, 96;" :: "r"(id) : "memory")

__device__ __forceinline__ unsigned smaddr(const void* p) {
    unsigned r;
    asm("{.reg .u64 t; cvta.to.shared.u64 t, %1; cvt.u32.u64 %0, t;}"
        : "=r"(r) : "l"(p));
    return r;
}

// ---------------------------------------------------------------------------
// Kernel A: FUSED single-pass q/k/v. 64 rows/block, 192 threads.
// Weights staged in 32-j chunks (Wcs[3][32][96] aliases old Ws buffer);
// featT read ONCE per j for all three matrices. rows[] aliases Wcs after
// the mainloop for the Q1/K1 epilogues.
// ---------------------------------------------------------------------------
#define A_FEATT 0            // 96*68 = 6528
#define A_WS    6528         // Wcs[3][32][96] = 9216 ; rows[64][100]=6400 alias
#define A_W1T   15744        // Ww1fT[6][100] = 600
#define A_FLOATS 16344

__global__ __launch_bounds__(192) void qkv_kernel(
    const float* __restrict__ feat, const float* __restrict__ coord,
    const float* __restrict__ Wq, const float* __restrict__ bq,
    const float* __restrict__ gq, const float* __restrict__ betaq,
    const float* __restrict__ Wk, const float* __restrict__ bk,
    const float* __restrict__ gk, const float* __restrict__ betak,
    const float* __restrict__ Wv, const float* __restrict__ bv,
    const float* __restrict__ Ww1, const float* __restrict__ gw,
    int n)
{
    extern __shared__ float sm[];
    float* featT = sm + A_FEATT;
    float* Wcs   = sm + A_WS;    // [3][32][96] chunk staging
    float* rows  = sm + A_WS;    // ALIAS (after mainloop)
    float* Ww1fT = sm + A_W1T;
    const int tid = threadIdx.x;
    const int tx = tid % 24, ty = tid / 24;
    const int base = blockIdx.x * 64;

    if (tid < 64) {
        int row = base + tid;
        if (row < n) {
            float4 c;
            c.x = coord[row * 3 + 0];
            c.y = coord[row * 3 + 1];
            c.z = coord[row * 3 + 2];
            c.w = 0.f;
            g_c4[row] = c;
        }
    }

    for (int i = tid; i < 64 * 96; i += 192) {
        int r = i / 96, j = i % 96;
        featT[j * 68 + r] = (base + r < n) ? feat[(base + r) * 96 + j] : 0.f;
    }
    for (int i = tid; i < 600; i += 192) {
        int g = i / 100, c = i % 100;
        Ww1fT[i] = (c < 96) ? Ww1[c * 6 + g] * (gw[g] * rsqrtf(1.00001f)) : 0.f;
    }

    const unsigned fbase  = smaddr(featT) + 8 * ty * 4;
    const unsigned rows_b = smaddr(rows);
    const unsigned w1t_b  = smaddr(Ww1fT);

    // accumulators for all three matrices: [m][row-pair][col]
    ull acc2[3][4][4];
    #pragma unroll
    for (int m = 0; m < 3; m++)
        #pragma unroll
        for (int p = 0; p < 4; p++)
            #pragma unroll
            for (int b = 0; b < 4; b++) acc2[m][p][b] = 0ULL;

    // ---- fused mainloop: 3 chunks of 32 j ----
    for (int ch = 0; ch < 3; ch++) {
        __syncthreads();
        // stage W chunk: Wcs[m][jj][c] = W_m[(32ch+jj)*96 + c]
        {
            int j0 = 32 * ch;
            for (int i = tid; i < 3072; i += 192) {
                int jj = i / 96, c = i % 96;
                Wcs[0 * 3072 + i] = Wq[(j0 + jj) * 96 + c];
                Wcs[1 * 3072 + i] = Wk[(j0 + jj) * 96 + c];
                Wcs[2 * 3072 + i] = Wv[(j0 + jj) * 96 + c];
            }
        }
        __syncthreads();

        unsigned fa = fbase + (32 * ch) * 68 * 4;
        #pragma unroll 2
        for (int jj = 0; jj < 32; jj++) {
            ull f01, f23, f45, f67;
            LDS2X64(f01, f23, fa);
            LDS2X64(f45, f67, fa + 16);
            fa += 272;
            #pragma unroll
            for (int m = 0; m < 3; m++) {
                float4 w4 = *(const float4*)&Wcs[m * 3072 + jj * 96 + 4 * tx];
                ull wd0, wd1, wd2, wd3;
                DUP2(wd0, w4.x); DUP2(wd1, w4.y); DUP2(wd2, w4.z); DUP2(wd3, w4.w);
                FFMA2(acc2[m][0][0], f01, wd0, acc2[m][0][0]);
                FFMA2(acc2[m][0][1], f01, wd1, acc2[m][0][1]);
                FFMA2(acc2[m][0][2], f01, wd2, acc2[m][0][2]);
                FFMA2(acc2[m][0][3], f01, wd3, acc2[m][0][3]);
                FFMA2(acc2[m][1][0], f23, wd0, acc2[m][1][0]);
                FFMA2(acc2[m][1][1], f23, wd1, acc2[m][1][1]);
                FFMA2(acc2[m][1][2], f23, wd2, acc2[m][1][2]);
                FFMA2(acc2[m][1][3], f23, wd3, acc2[m][1][3]);
                FFMA2(acc2[m][2][0], f45, wd0, acc2[m][2][0]);
                FFMA2(acc2[m][2][1], f45, wd1, acc2[m][2][1]);
                FFMA2(acc2[m][2][2], f45, wd2, acc2[m][2][2]);
                FFMA2(acc2[m][2][3], f45, wd3, acc2[m][2][3]);
                FFMA2(acc2[m][3][0], f67, wd0, acc2[m][3][0]);
                FFMA2(acc2[m][3][1], f67, wd1, acc2[m][3][1]);
                FFMA2(acc2[m][3][2], f67, wd2, acc2[m][3][2]);
                FFMA2(acc2[m][3][3], f67, wd3, acc2[m][3][3]);
            }
        }
    }

    // ---- epilogue v (m=2): direct store ----
    {
        int c = 4 * tx;
        float4 bb = *(const float4*)&bv[c];
        #pragma unroll
        for (int p = 0; p < 4; p++) {
            float alo[4], ahi[4];
            #pragma unroll
            for (int b = 0; b < 4; b++) UNPK(alo[b], ahi[b], acc2[2][p][b]);
            int row0 = base + 8 * ty + 2 * p;
            if (row0 < n) {
                float4 o = {alo[0] + bb.x, alo[1] + bb.y, alo[2] + bb.z, alo[3] + bb.w};
                *(float4*)&g_v[row0 * 96 + c] = o;
            }
            if (row0 + 1 < n) {
                float4 o = {ahi[0] + bb.x, ahi[1] + bb.y, ahi[2] + bb.z, ahi[3] + bb.w};
                *(float4*)&g_v[(row0 + 1) * 96 + c] = o;
            }
        }
    }

    // ---- epilogues q (m=0) and k (m=1): bn+relu -> rows -> Q1/K1 ----
    for (int m = 0; m < 2; m++) {
        int c = 4 * tx;
        const float* bsrc = (m == 0) ? bq : bk;
        const float* gsrc = (m == 0) ? gq : gk;
        const float* besrc = (m == 0) ? betaq : betak;
        float4 bb = *(const float4*)&bsrc[c];
        float4 gg = *(const float4*)&gsrc[c];
        float4 be = *(const float4*)&besrc[c];
        float rs = rsqrtf(1.00001f);
        float aa[4] = {gg.x * rs, gg.y * rs, gg.z * rs, gg.w * rs};
        float bba[4] = {bb.x, bb.y, bb.z, bb.w};
        float bea[4] = {be.x, be.y, be.z, be.w};
        __syncthreads();     // rows alias region free (Wcs dead / prior pass done)
        #pragma unroll
        for (int p = 0; p < 4; p++) {
            float alo[4], ahi[4];
            #pragma unroll
            for (int b = 0; b < 4; b++) UNPK(alo[b], ahi[b], acc2[m][p][b]);
            float4 o0, o1;
            o0.x = fmaxf((alo[0] + bba[0]) * aa[0] + bea[0], 0.f);
            o0.y = fmaxf((alo[1] + bba[1]) * aa[1] + bea[1], 0.f);
            o0.z = fmaxf((alo[2] + bba[2]) * aa[2] + bea[2], 0.f);
            o0.w = fmaxf((alo[3] + bba[3]) * aa[3] + bea[3], 0.f);
            o1.x = fmaxf((ahi[0] + bba[0]) * aa[0] + bea[0], 0.f);
            o1.y = fmaxf((ahi[1] + bba[1]) * aa[1] + bea[1], 0.f);
            o1.z = fmaxf((ahi[2] + bba[2]) * aa[2] + bea[2], 0.f);
            o1.w = fmaxf((ahi[3] + bba[3]) * aa[3] + bea[3], 0.f);
            *(float4*)&rows[(8 * ty + 2 * p) * 100 + c]     = o0;
            *(float4*)&rows[(8 * ty + 2 * p + 1) * 100 + c] = o1;
        }
        __syncthreads();
        float* dst = (m == 0) ? g_Q1 : g_K1;
        #pragma unroll
        for (int rr = 0; rr < 2; rr++) {
            int i = rr * 192 + tid;
            int r = i / 6, g = i % 6;
            ull a01 = 0ULL, a23 = 0ULL;
            unsigned rb = rows_b + r * 400;
            unsigned wb = w1t_b + g * 400;
            #pragma unroll
            for (int t = 0; t < 24; t++) {
                ull r01, r23, w01, w23;
                LDS2X64(r01, r23, rb); rb += 16;
                LDS2X64(w01, w23, wb); wb += 16;
                FFMA2(a01, r01, w01, a01);
                FFMA2(a23, r23, w23, a23);
            }
            float l0, l1v, l2v, l3;
            UNPK(l0, l1v, a01); UNPK(l2v, l3, a23);
            if (base + r < n)
                dst[(base + r) * 8 + g] = (l0 + l2v) + (l1v + l3);
        }
    }
}

// ---------------------------------------------------------------------------
// Kernel B: fused attention (R10 verbatim — proven 239.5us).
// ---------------------------------------------------------------------------
#define SH_WP2T 0        // [96][100]
#define SH_FT   9600     // [6][100]
#define SH_WP1F 10200    // [96][4]
#define SH_BP2  10584    // 96
#define SH_WW2  10680    // 40
#define SH_BW2  10720    // 8
#define SH_CB   10728    // 8
#define SH_W1F  10736    // 576
#define SH_PART 11312    // [16][96]
#define SH_LANE 12848
// per-lane (floats)
#define L_HT   0         // hT[16][100]; aliased as At[6][100] later
#define L_PB   1600      // Pb[3][16][8] = 384
#define L_WH   1984      // [16][8]
#define L_LW   2112      // [16][8]
#define L_POS  2240      // 2 x [16][4]
#define L_MSK  2368      // 2 x 16
#define L_SW   2400      // 8
#define L_K1S  2408      // 2 x [16][8]
#define L_IDX  2664      // 2 x 16 ints
#define LZ     2720
#define B_FLOATS (SH_LANE + 4 * LZ)   // 23728 floats = 94.9 KB

__global__ __launch_bounds__(384, 2) void attn_kernel(
    const int* __restrict__ refidx,
    const float* __restrict__ Wp1, const float* __restrict__ bp1,
    const float* __restrict__ gp,  const float* __restrict__ betap,
    const float* __restrict__ Wp2, const float* __restrict__ bp2,
    const float* __restrict__ Ww1, const float* __restrict__ bw1,
    const float* __restrict__ gw,  const float* __restrict__ betaw,
    const float* __restrict__ Ww2, const float* __restrict__ bw2,
    float* __restrict__ out, int n)
{
    extern __shared__ float sm[];
    float* Wp2T  = sm + SH_WP2T;
    float* Fts   = sm + SH_FT;
    float* Wp1f  = sm + SH_WP1F;
    float* bp2s  = sm + SH_BP2;
    float* Ww2s  = sm + SH_WW2;
    float* bw2s  = sm + SH_BW2;
    float* CBs   = sm + SH_CB;
    float* Ww1fs = sm + SH_W1F;
    float* part  = sm + SH_PART;

    const int tid  = threadIdx.x;
    const int pp   = tid / 96;
    const int jr   = tid % 96;
    const int wl   = jr / 32;
    const int lane = tid & 31;
    const int sL   = jr & 15, gL = jr >> 4;
    const int barid = 1 + pp;

    float* lzone = sm + SH_LANE + pp * LZ;
    float* hT    = lzone + L_HT;
    float* At    = lzone + L_HT;
    float* Pb    = lzone + L_PB;
    float* whes  = lzone + L_WH;
    float* l2w   = lzone + L_LW;
    float* poss  = lzone + L_POS;
    float* masks = lzone + L_MSK;
    float* swv   = lzone + L_SW;
    float* K1s   = lzone + L_K1S;
    int*   idxp  = (int*)(lzone + L_IDX);

    const unsigned sb     = smaddr(sm);
    const unsigned ht_b   = sb + 4 * (SH_LANE + pp * LZ + L_HT);
    const unsigned lw_b   = sb + 4 * (SH_LANE + pp * LZ + L_LW);
    const unsigned ft_b   = sb + 4 * SH_FT;
    const unsigned wp2_b  = sb + 4 * SH_WP2T;

    // ---- one-time staging ----
    for (int i = tid; i < 9216; i += 384)
        Wp2T[(i % 96) * 100 + i / 96] = Wp2[i];
    if (tid < 96) {
        float ap = gp[tid] * rsqrtf(1.00001f);
        Wp1f[tid * 4 + 0] = Wp1[tid]       * ap;
        Wp1f[tid * 4 + 1] = Wp1[96 + tid]  * ap;
        Wp1f[tid * 4 + 2] = Wp1[192 + tid] * ap;
        Wp1f[tid * 4 + 3] = bp1[tid] * ap + betap[tid];
        bp2s[tid] = bp2[tid];
    }
    if (tid < 36) Ww2s[tid] = Ww2[tid];
    if (tid < 6)  bw2s[tid] = bw2[tid];
    for (int i = tid; i < 576; i += 384) {
        int g = i % 6;
        Ww1fs[i] = Ww1[i] * (gw[g] * rsqrtf(1.00001f));
    }
    __syncthreads();
    for (int i = tid; i < 576; i += 384) {
        int j = i / 6, g = i % 6;
        float f = 0.f;
        #pragma unroll 8
        for (int c = 0; c < 96; c++) f += Wp2T[c * 100 + j] * Ww1fs[c * 6 + g];
        Fts[g * 100 + j] = f;
    }
    if (tid < 6) {
        float aw = gw[tid] * rsqrtf(1.00001f);
        float cb = bw1[tid] * aw + betaw[tid];
        for (int c = 0; c < 96; c++) cb += bp2s[c] * Ww1fs[c * 6 + tid];
        CBs[tid] = cb;
    }
    __syncthreads();

    // ---- ph1 loader (warp0: pos/mask/idx; warp1: K1), buffer b ----
    auto load_ph1 = [&](int nn2, int b) {
        if (nn2 < n && lane < 16) {
            if (wl == 0) {
                int raw = refidx[nn2 * 16 + lane];
                int vv = raw + 1;
                masks[b * 16 + lane] = (vv > 0) ? 1.f : ((vv < 0) ? -1.f : 0.f);
                int idx = (raw < 0) ? raw + n : raw;
                idxp[b * 16 + lane] = idx;
                float4 c0 = g_c4[nn2];
                float4 cn = g_c4[idx];
                poss[b * 64 + lane * 4 + 0] = cn.x - c0.x;
                poss[b * 64 + lane * 4 + 1] = cn.y - c0.y;
                poss[b * 64 + lane * 4 + 2] = cn.z - c0.z;
            } else if (wl == 1) {
                int raw = refidx[nn2 * 16 + lane];
                int idx = (raw < 0) ? raw + n : raw;
                float4 ka = *(const float4*)&g_K1[idx * 8];
                float4 kb = *(const float4*)&g_K1[idx * 8 + 4];
                *(float4*)&K1s[b * 128 + lane * 8] = ka;
                *(float4*)&K1s[b * 128 + lane * 8 + 4] = kb;
            }
        }
    };

    load_ph1(blockIdx.x * 4 + pp, 0);

    int par = 0;
    for (int it = blockIdx.x; it * 4 < n; it += gridDim.x) {
        int nn = it * 4 + pp;
        bool act = (nn < n);

        LANE_BAR(barid);   // ph1[par] visible to this lane

        // ---- ph2: h[s] per thread-j ----
        float h[16];
        if (act) {
            float4 wp = *(const float4*)&Wp1f[jr * 4];
            #pragma unroll
            for (int s = 0; s < 16; s++) {
                float4 p = *(const float4*)&poss[par * 64 + s * 4];
                float hv = fmaxf(wp.w + p.x * wp.x + p.y * wp.y + p.z * wp.z, 0.f);
                h[s] = hv;
                hT[s * 100 + jr] = hv;
            }
        }
        __syncwarp();

        // ---- ph3: l1 partials, j-split across warps ----
        if (act) {
            int s = lane & 15, gt = lane >> 4;
            int j0 = 32 * wl;
            ull ag0 = 0ULL, ag1 = 0ULL, ag2 = 0ULL;
            unsigned hb  = ht_b + (s * 100 + j0) * 4;
            unsigned f0b = ft_b + ((gt * 3 + 0) * 100 + j0) * 4;
            unsigned f1b = f0b + 400;
            unsigned f2b = f1b + 400;
            #pragma unroll
            for (int t = 0; t < 8; t++) {
                ull h01, h23, f01, f23;
                LDS2X64(h01, h23, hb); hb += 16;
                LDS2X64(f01, f23, f0b); f0b += 16;
                FFMA2(ag0, h01, f01, ag0);
                FFMA2(ag0, h23, f23, ag0);
                LDS2X64(f01, f23, f1b); f1b += 16;
                FFMA2(ag1, h01, f01, ag1);
                FFMA2(ag1, h23, f23, ag1);
                LDS2X64(f01, f23, f2b); f2b += 16;
                FFMA2(ag2, h01, f01, ag2);
                FFMA2(ag2, h23, f23, ag2);
            }
            float x0, x1;
            float* pb = Pb + wl * 128 + s * 8 + gt * 4;
            UNPK(x0, x1, ag0); pb[0] = x0 + x1;
            UNPK(x0, x1, ag1); pb[1] = x0 + x1;
            UNPK(x0, x1, ag2); pb[2] = x0 + x1;
        }
        LANE_BAR(barid);

        // ---- ph3b: combine partials + K1/Q1, wh = relu(l1) ----
        if (act) {
            int slot = gL + (gL >= 3 ? 1 : 0);
            float l1 = CBs[gL] + K1s[par * 128 + sL * 8 + gL] - g_Q1[nn * 8 + gL]
                     + Pb[0 * 128 + sL * 8 + slot]
                     + Pb[1 * 128 + sL * 8 + slot]
                     + Pb[2 * 128 + sL * 8 + slot];
            whes[sL * 8 + gL] = fmaxf(l1, 0.f);
        }
        LANE_BAR(barid);

        // ---- ph456: l2, 16-lane softmax, masked weights ----
        if (act) {
            float l2 = bw2s[gL];
            #pragma unroll
            for (int gg = 0; gg < 6; gg++)
                l2 += whes[sL * 8 + gg] * Ww2s[gg * 6 + gL];
            float mx = l2;
            #pragma unroll
            for (int off = 8; off >= 1; off >>= 1)
                mx = fmaxf(mx, __shfl_xor_sync(0xffffffffu, mx, off, 16));
            float e  = __expf(l2 - mx);
            float em = e * masks[par * 16 + sL];
            float ss = e, ms = em;
            #pragma unroll
            for (int off = 8; off >= 1; off >>= 1) {
                ss += __shfl_xor_sync(0xffffffffu, ss, off, 16);
                ms += __shfl_xor_sync(0xffffffffu, ms, off, 16);
            }
            l2w[sL * 8 + gL] = em / ss;
            if (sL == 0) swv[gL] = ms / ss;
        }
        LANE_BAR(barid);

        // ---- prefetch next iteration's ph1 (overlaps ph7/8) ----
        load_ph1((it + gridDim.x) * 4 + pp, par ^ 1);

        // ---- ph7: A[j,g] = sum_s h[s,j] w[s,g]  (f32x2) ----
        if (act) {
            ull A01 = 0ULL, A23 = 0ULL, A45 = 0ULL;
            unsigned lb = lw_b;
            #pragma unroll
            for (int s = 0; s < 16; s++) {
                ull w01, w23, w45, w67;
                LDS2X64(w01, w23, lb);
                LDS2X64(w45, w67, lb + 16);
                lb += 32;
                ull hd; DUP2(hd, h[s]);
                FFMA2(A01, hd, w01, A01);
                FFMA2(A23, hd, w23, A23);
                FFMA2(A45, hd, w45, A45);
            }
            float A0, A1, A2, A3, A4, A5;
            UNPK(A0, A1, A01);
            UNPK(A2, A3, A23);
            UNPK(A4, A5, A45);
            At[0 * 100 + jr] = A0; At[1 * 100 + jr] = A1; At[2 * 100 + jr] = A2;
            At[3 * 100 + jr] = A3; At[4 * 100 + jr] = A4; At[5 * 100 + jr] = A5;
        }
        __syncthreads();

        // ---- ph8a: quartered Wp2^T @ A across 4 points (f32x2) ----
        {
            int c = jr, g = jr >> 4, j0 = pp * 24;
            ull pt2[4] = {0ULL, 0ULL, 0ULL, 0ULL};
            unsigned wb = wp2_b + (c * 100 + j0) * 4;
            unsigned ab0 = sb + 4 * (SH_LANE + 0 * LZ + L_HT) + (g * 100 + j0) * 4;
            unsigned ab1 = sb + 4 * (SH_LANE + 1 * LZ + L_HT) + (g * 100 + j0) * 4;
            unsigned ab2 = sb + 4 * (SH_LANE + 2 * LZ + L_HT) + (g * 100 + j0) * 4;
            unsigned ab3 = sb + 4 * (SH_LANE + 3 * LZ + L_HT) + (g * 100 + j0) * 4;
            #pragma unroll
            for (int t = 0; t < 6; t++) {
                ull w01, w23, a01, a23;
                LDS2X64(w01, w23, wb); wb += 16;
                LDS2X64(a01, a23, ab0); ab0 += 16;
                FFMA2(pt2[0], w01, a01, pt2[0]);
                FFMA2(pt2[0], w23, a23, pt2[0]);
                LDS2X64(a01, a23, ab1); ab1 += 16;
                FFMA2(pt2[1], w01, a01, pt2[1]);
                FFMA2(pt2[1], w23, a23, pt2[1]);
                LDS2X64(a01, a23, ab2); ab2 += 16;
                FFMA2(pt2[2], w01, a01, pt2[2]);
                FFMA2(pt2[2], w23, a23, pt2[2]);
                LDS2X64(a01, a23, ab3); ab3 += 16;
                FFMA2(pt2[3], w01, a01, pt2[3]);
                FFMA2(pt2[3], w23, a23, pt2[3]);
            }
            #pragma unroll
            for (int p = 0; p < 4; p++) {
                float lo, hi;
                UNPK(lo, hi, pt2[p]);
                part[(pp * 4 + p) * 96 + c] = lo + hi;
            }
        }
        __syncthreads();

        // ---- ph8b: combine quarters + v-gather term, store out ----
        if (act) {
            int c = jr, g = jr >> 4;
            const int* idq = (const int*)(lzone + L_IDX) + par * 16;
            float o = bp2s[c] * swv[g];
            o += part[(0 * 4 + pp) * 96 + c] + part[(1 * 4 + pp) * 96 + c]
               + part[(2 * 4 + pp) * 96 + c] + part[(3 * 4 + pp) * 96 + c];
            float vv[16];
            #pragma unroll
            for (int s = 0; s < 16; s++)
                vv[s] = g_v[idq[s] * 96 + c];
            #pragma unroll
            for (int s = 0; s < 16; s++)
                o += vv[s] * l2w[s * 8 + g];
            out[nn * 96 + c] = o;
        }
        par ^= 1;
    }
}

extern "C" void kernel_launch(void* const* d_in, const int* in_sizes, int n_in,
                              void* d_out, int out_size) {
    const float* feat  = (const float*)d_in[0];
    const float* coord = (const float*)d_in[1];
    const int*   ref   = (const int*)d_in[2];
    const float* Wq    = (const float*)d_in[3];
    const float* bq    = (const float*)d_in[4];
    const float* gq    = (const float*)d_in[5];
    const float* betaq = (const float*)d_in[6];
    const float* Wk    = (const float*)d_in[7];
    const float* bk    = (const float*)d_in[8];
    const float* gk    = (const float*)d_in[9];
    const float* betak = (const float*)d_in[10];
    const float* Wv    = (const float*)d_in[11];
    const float* bv    = (const float*)d_in[12];
    const float* Wp1   = (const float*)d_in[13];
    const float* bp1   = (const float*)d_in[14];
    const float* gp    = (const float*)d_in[15];
    const float* betap = (const float*)d_in[16];
    const float* Wp2   = (const float*)d_in[17];
    const float* bp2   = (const float*)d_in[18];
    const float* Ww1   = (const float*)d_in[19];
    const float* bw1   = (const float*)d_in[20];
    const float* gw    = (const float*)d_in[21];
    const float* betaw = (const float*)d_in[22];
    const float* Ww2   = (const float*)d_in[23];
    const float* bw2   = (const float*)d_in[24];

    int n = in_sizes[1] / 3;

    int smA = A_FLOATS * (int)sizeof(float);
    int smB = B_FLOATS * (int)sizeof(float);
    cudaFuncSetAttribute(qkv_kernel,  cudaFuncAttributeMaxDynamicSharedMemorySize, smA);
    cudaFuncSetAttribute(attn_kernel, cudaFuncAttributeMaxDynamicSharedMemorySize, smB);

    int blocksA = (n + 63) / 64;
    qkv_kernel<<<blocksA, 192, smA>>>(feat, coord, Wq, bq, gq, betaq,
                                      Wk, bk, gk, betak, Wv, bv, Ww1, gw, n);

    int occ = 0;
    cudaOccupancyMaxActiveBlocksPerMultiprocessor(&occ, attn_kernel, 384, smB);
    if (occ < 1) occ = 1;
    int nsm = 0;
    cudaDeviceGetAttribute(&nsm, cudaDevAttrMultiProcessorCount, 0);
    if (nsm <= 0) nsm = 148;
    int blocksB = occ * nsm;
    int quads = (n + 3) / 4;
    if (blocksB > quads) blocksB = quads;

    attn_kernel<<<blocksB, 384, smB>>>(ref,
                                       Wp1, bp1, gp, betap, Wp2, bp2,
                                       Ww1, bw1, gw, betaw, Ww2, bw2,
                                       (float*)d_out, n);
}

// round 15
// speedup vs baseline: 1.0353x; 1.0156x over previous
#include <cuda_runtime.h>

#define NMAX 50000
#define C 96

__device__ float g_v[NMAX * C];
__device__ float g_Q1[NMAX * 8];
__device__ float g_K1[NMAX * 8];
__device__ float4 g_c4[NMAX];

// ---- f32x2 packed-math helpers (sm_103a) ----
typedef unsigned long long ull;
#define FFMA2(d, a, b, c) \
    asm("fma.rn.f32x2 %0, %1, %2, %3;" : "=l"(d) : "l"(a), "l"(b), "l"(c))
#define LDS2X64(a, b, addr) \
    asm volatile("ld.shared.v2.u64 {%0, %1}, [%2];" : "=l"(a), "=l"(b) : "r"(addr))
#define DUP2(d, f) \
    asm("mov.b64 %0, {%1, %1};" : "=l"(d) : "r"(__float_as_uint(f)))
#define UNPK(lo, hi, p) do { unsigned _ul, _uh; \
    asm("mov.b64 {%0, %1}, %2;" : "=r"(_ul), "=r"(_uh) : "l"(p)); \
    lo = __uint_as_float(_ul); hi = __uint_as_float(_uh); } while (0)
#define LANE_BAR(id) \
    asm volatile("bar.sync %0, 96;" :: "r"(id) : "memory")

__device__ __forceinline__ unsigned smaddr(const void* p) {
    unsigned r;
    asm("{.reg .u64 t; cvta.to.shared.u64 t, %1; cvt.u32.u64 %0, t;}"
        : "=r"(r) : "l"(p));
    return r;
}

// ---------------------------------------------------------------------------
// Kernel A: v, Q1, K1. R10 mainloop; NEW epilogue: register partials for
// Q1/K1 (24 Ww1f regs/thread) + pitch-147 part2 + 24-way scalar reduction.
// part2[64][147] aliases the Ws staging buffer.
// ---------------------------------------------------------------------------
#define A_FEATT 0            // 96*68 = 6528
#define A_WS    6528         // Ws 96*96=9216 ; part2[64][147]=9408 alias
#define A_W1T   15936        // Ww1fT[6][100] = 600
#define A_FLOATS 16536

__global__ __launch_bounds__(192) void qkv_kernel(
    const float* __restrict__ feat, const float* __restrict__ coord,
    const float* __restrict__ Wq, const float* __restrict__ bq,
    const float* __restrict__ gq, const float* __restrict__ betaq,
    const float* __restrict__ Wk, const float* __restrict__ bk,
    const float* __restrict__ gk, const float* __restrict__ betak,
    const float* __restrict__ Wv, const float* __restrict__ bv,
    const float* __restrict__ Ww1, const float* __restrict__ gw,
    int n)
{
    extern __shared__ float sm[];
    float* featT = sm + A_FEATT;
    float* Ws    = sm + A_WS;
    float* part2 = sm + A_WS;    // ALIAS: live only after mainloop per m
    float* Ww1fT = sm + A_W1T;
    const int tid = threadIdx.x;
    const int tx = tid % 24, ty = tid / 24;
    const int base = blockIdx.x * 64;

    if (tid < 64) {
        int row = base + tid;
        if (row < n) {
            float4 c;
            c.x = coord[row * 3 + 0];
            c.y = coord[row * 3 + 1];
            c.z = coord[row * 3 + 2];
            c.w = 0.f;
            g_c4[row] = c;
        }
    }

    for (int i = tid; i < 64 * 96; i += 192) {
        int r = i / 96, j = i % 96;
        featT[j * 68 + r] = (base + r < n) ? feat[(base + r) * 96 + j] : 0.f;
    }
    for (int i = tid; i < 600; i += 192) {
        int g = i / 100, c = i % 100;
        Ww1fT[i] = (c < 96) ? Ww1[c * 6 + g] * (gw[g] * rsqrtf(1.00001f)) : 0.f;
    }
    __syncthreads();

    // register-resident Ww1f for this thread's 4 channels: w1r[b*6+g]
    float w1r[24];
    #pragma unroll
    for (int b = 0; b < 4; b++)
        #pragma unroll
        for (int g = 0; g < 6; g++)
            w1r[b * 6 + g] = Ww1fT[g * 100 + 4 * tx + b];

    const unsigned fbase = smaddr(featT) + 8 * ty * 4;

    for (int m = 0; m < 3; m++) {
        const float* W = (m == 0) ? Wq : ((m == 1) ? Wk : Wv);
        __syncthreads();     // prior epilogue done before Ws overwrite
        for (int i = tid; i < 96 * 96; i += 192) Ws[i] = W[i];
        __syncthreads();

        ull acc2[4][4];
        #pragma unroll
        for (int p = 0; p < 4; p++)
            #pragma unroll
            for (int b = 0; b < 4; b++) acc2[p][b] = 0ULL;

        unsigned fa = fbase;
        #pragma unroll 4
        for (int j = 0; j < 96; j++) {
            ull f01, f23, f45, f67;
            LDS2X64(f01, f23, fa);
            LDS2X64(f45, f67, fa + 16);
            fa += 272;
            float4 w4 = *(const float4*)&Ws[j * 96 + 4 * tx];
            ull wd0, wd1, wd2, wd3;
            DUP2(wd0, w4.x); DUP2(wd1, w4.y); DUP2(wd2, w4.z); DUP2(wd3, w4.w);
            FFMA2(acc2[0][0], f01, wd0, acc2[0][0]);
            FFMA2(acc2[0][1], f01, wd1, acc2[0][1]);
            FFMA2(acc2[0][2], f01, wd2, acc2[0][2]);
            FFMA2(acc2[0][3], f01, wd3, acc2[0][3]);
            FFMA2(acc2[1][0], f23, wd0, acc2[1][0]);
            FFMA2(acc2[1][1], f23, wd1, acc2[1][1]);
            FFMA2(acc2[1][2], f23, wd2, acc2[1][2]);
            FFMA2(acc2[1][3], f23, wd3, acc2[1][3]);
            FFMA2(acc2[2][0], f45, wd0, acc2[2][0]);
            FFMA2(acc2[2][1], f45, wd1, acc2[2][1]);
            FFMA2(acc2[2][2], f45, wd2, acc2[2][2]);
            FFMA2(acc2[2][3], f45, wd3, acc2[2][3]);
            FFMA2(acc2[3][0], f67, wd0, acc2[3][0]);
            FFMA2(acc2[3][1], f67, wd1, acc2[3][1]);
            FFMA2(acc2[3][2], f67, wd2, acc2[3][2]);
            FFMA2(acc2[3][3], f67, wd3, acc2[3][3]);
        }

        if (m == 2) {
            int c = 4 * tx;
            float4 bb = *(const float4*)&bv[c];
            #pragma unroll
            for (int p = 0; p < 4; p++) {
                float alo[4], ahi[4];
                #pragma unroll
                for (int b = 0; b < 4; b++) UNPK(alo[b], ahi[b], acc2[p][b]);
                int r0 = base + 8 * ty + 2 * p;
                if (r0 < n) {
                    float4 o = {alo[0] + bb.x, alo[1] + bb.y,
                                alo[2] + bb.z, alo[3] + bb.w};
                    *(float4*)&g_v[r0 * 96 + c] = o;
                }
                if (r0 + 1 < n) {
                    float4 o = {ahi[0] + bb.x, ahi[1] + bb.y,
                                ahi[2] + bb.z, ahi[3] + bb.w};
                    *(float4*)&g_v[(r0 + 1) * 96 + c] = o;
                }
            }
        } else {
            int c = 4 * tx;
            const float* bsrc = (m == 0) ? bq : bk;
            const float* gsrc = (m == 0) ? gq : gk;
            const float* besrc = (m == 0) ? betaq : betak;
            float4 bb = *(const float4*)&bsrc[c];
            float4 gg = *(const float4*)&gsrc[c];
            float4 be = *(const float4*)&besrc[c];
            float rs = rsqrtf(1.00001f);
            float aa[4] = {gg.x * rs, gg.y * rs, gg.z * rs, gg.w * rs};
            float bba[4] = {bb.x, bb.y, bb.z, bb.w};
            float bea[4] = {be.x, be.y, be.z, be.w};
            __syncthreads();     // all warps done reading Ws before part2 write
            #pragma unroll
            for (int p = 0; p < 4; p++) {
                float alo[4], ahi[4];
                #pragma unroll
                for (int b = 0; b < 4; b++) UNPK(alo[b], ahi[b], acc2[p][b]);
                float v0[4], v1[4];
                #pragma unroll
                for (int b = 0; b < 4; b++) {
                    v0[b] = fmaxf((alo[b] + bba[b]) * aa[b] + bea[b], 0.f);
                    v1[b] = fmaxf((ahi[b] + bba[b]) * aa[b] + bea[b], 0.f);
                }
                float* p2 = part2 + (8 * ty + 2 * p) * 147;
                #pragma unroll
                for (int g = 0; g < 6; g++) {
                    float s0 = v0[0] * w1r[g] + v0[1] * w1r[6 + g]
                             + v0[2] * w1r[12 + g] + v0[3] * w1r[18 + g];
                    float s1 = v1[0] * w1r[g] + v1[1] * w1r[6 + g]
                             + v1[2] * w1r[12 + g] + v1[3] * w1r[18 + g];
                    p2[g * 24 + tx]       = s0;
                    p2[147 + g * 24 + tx] = s1;
                }
            }
            __syncthreads();
            float* dst = (m == 0) ? g_Q1 : g_K1;
            #pragma unroll
            for (int rr = 0; rr < 2; rr++) {
                int i = rr * 192 + tid;
                int r = i / 6, g = i % 6;
                const float* src = part2 + r * 147 + g * 24;
                float s = 0.f;
                #pragma unroll
                for (int t = 0; t < 24; t++) s += src[t];
                if (base + r < n) dst[(base + r) * 8 + g] = s;
            }
        }
    }
}

// ---------------------------------------------------------------------------
// Kernel B: fused attention (R10 verbatim — proven).
// ---------------------------------------------------------------------------
#define SH_WP2T 0        // [96][100]
#define SH_FT   9600     // [6][100]
#define SH_WP1F 10200    // [96][4]
#define SH_BP2  10584    // 96
#define SH_WW2  10680    // 40
#define SH_BW2  10720    // 8
#define SH_CB   10728    // 8
#define SH_W1F  10736    // 576
#define SH_PART 11312    // [16][96]
#define SH_LANE 12848
#define L_HT   0
#define L_PB   1600
#define L_WH   1984
#define L_LW   2112
#define L_POS  2240
#define L_MSK  2368
#define L_SW   2400
#define L_K1S  2408
#define L_IDX  2664
#define LZ     2720
#define B_FLOATS (SH_LANE + 4 * LZ)

__global__ __launch_bounds__(384, 2) void attn_kernel(
    const int* __restrict__ refidx,
    const float* __restrict__ Wp1, const float* __restrict__ bp1,
    const float* __restrict__ gp,  const float* __restrict__ betap,
    const float* __restrict__ Wp2, const float* __restrict__ bp2,
    const float* __restrict__ Ww1, const float* __restrict__ bw1,
    const float* __restrict__ gw,  const float* __restrict__ betaw,
    const float* __restrict__ Ww2, const float* __restrict__ bw2,
    float* __restrict__ out, int n)
{
    extern __shared__ float sm[];
    float* Wp2T  = sm + SH_WP2T;
    float* Fts   = sm + SH_FT;
    float* Wp1f  = sm + SH_WP1F;
    float* bp2s  = sm + SH_BP2;
    float* Ww2s  = sm + SH_WW2;
    float* bw2s  = sm + SH_BW2;
    float* CBs   = sm + SH_CB;
    float* Ww1fs = sm + SH_W1F;
    float* part  = sm + SH_PART;

    const int tid  = threadIdx.x;
    const int pp   = tid / 96;
    const int jr   = tid % 96;
    const int wl   = jr / 32;
    const int lane = tid & 31;
    const int sL   = jr & 15, gL = jr >> 4;
    const int barid = 1 + pp;

    float* lzone = sm + SH_LANE + pp * LZ;
    float* hT    = lzone + L_HT;
    float* At    = lzone + L_HT;
    float* Pb    = lzone + L_PB;
    float* whes  = lzone + L_WH;
    float* l2w   = lzone + L_LW;
    float* poss  = lzone + L_POS;
    float* masks = lzone + L_MSK;
    float* swv   = lzone + L_SW;
    float* K1s   = lzone + L_K1S;
    int*   idxp  = (int*)(lzone + L_IDX);

    const unsigned sb     = smaddr(sm);
    const unsigned ht_b   = sb + 4 * (SH_LANE + pp * LZ + L_HT);
    const unsigned lw_b   = sb + 4 * (SH_LANE + pp * LZ + L_LW);
    const unsigned ft_b   = sb + 4 * SH_FT;
    const unsigned wp2_b  = sb + 4 * SH_WP2T;

    for (int i = tid; i < 9216; i += 384)
        Wp2T[(i % 96) * 100 + i / 96] = Wp2[i];
    if (tid < 96) {
        float ap = gp[tid] * rsqrtf(1.00001f);
        Wp1f[tid * 4 + 0] = Wp1[tid]       * ap;
        Wp1f[tid * 4 + 1] = Wp1[96 + tid]  * ap;
        Wp1f[tid * 4 + 2] = Wp1[192 + tid] * ap;
        Wp1f[tid * 4 + 3] = bp1[tid] * ap + betap[tid];
        bp2s[tid] = bp2[tid];
    }
    if (tid < 36) Ww2s[tid] = Ww2[tid];
    if (tid < 6)  bw2s[tid] = bw2[tid];
    for (int i = tid; i < 576; i += 384) {
        int g = i % 6;
        Ww1fs[i] = Ww1[i] * (gw[g] * rsqrtf(1.00001f));
    }
    __syncthreads();
    for (int i = tid; i < 576; i += 384) {
        int j = i / 6, g = i % 6;
        float f = 0.f;
        #pragma unroll 8
        for (int c = 0; c < 96; c++) f += Wp2T[c * 100 + j] * Ww1fs[c * 6 + g];
        Fts[g * 100 + j] = f;
    }
    if (tid < 6) {
        float aw = gw[tid] * rsqrtf(1.00001f);
        float cb = bw1[tid] * aw + betaw[tid];
        for (int c = 0; c < 96; c++) cb += bp2s[c] * Ww1fs[c * 6 + tid];
        CBs[tid] = cb;
    }
    __syncthreads();

    auto load_ph1 = [&](int nn2, int b) {
        if (nn2 < n && lane < 16) {
            if (wl == 0) {
                int raw = refidx[nn2 * 16 + lane];
                int vv = raw + 1;
                masks[b * 16 + lane] = (vv > 0) ? 1.f : ((vv < 0) ? -1.f : 0.f);
                int idx = (raw < 0) ? raw + n : raw;
                idxp[b * 16 + lane] = idx;
                float4 c0 = g_c4[nn2];
                float4 cn = g_c4[idx];
                poss[b * 64 + lane * 4 + 0] = cn.x - c0.x;
                poss[b * 64 + lane * 4 + 1] = cn.y - c0.y;
                poss[b * 64 + lane * 4 + 2] = cn.z - c0.z;
            } else if (wl == 1) {
                int raw = refidx[nn2 * 16 + lane];
                int idx = (raw < 0) ? raw + n : raw;
                float4 ka = *(const float4*)&g_K1[idx * 8];
                float4 kb = *(const float4*)&g_K1[idx * 8 + 4];
                *(float4*)&K1s[b * 128 + lane * 8] = ka;
                *(float4*)&K1s[b * 128 + lane * 8 + 4] = kb;
            }
        }
    };

    load_ph1(blockIdx.x * 4 + pp, 0);

    int par = 0;
    for (int it = blockIdx.x; it * 4 < n; it += gridDim.x) {
        int nn = it * 4 + pp;
        bool act = (nn < n);

        LANE_BAR(barid);

        float h[16];
        if (act) {
            float4 wp = *(const float4*)&Wp1f[jr * 4];
            #pragma unroll
            for (int s = 0; s < 16; s++) {
                float4 p = *(const float4*)&poss[par * 64 + s * 4];
                float hv = fmaxf(wp.w + p.x * wp.x + p.y * wp.y + p.z * wp.z, 0.f);
                h[s] = hv;
                hT[s * 100 + jr] = hv;
            }
        }
        __syncwarp();

        if (act) {
            int s = lane & 15, gt = lane >> 4;
            int j0 = 32 * wl;
            ull ag0 = 0ULL, ag1 = 0ULL, ag2 = 0ULL;
            unsigned hb  = ht_b + (s * 100 + j0) * 4;
            unsigned f0b = ft_b + ((gt * 3 + 0) * 100 + j0) * 4;
            unsigned f1b = f0b + 400;
            unsigned f2b = f1b + 400;
            #pragma unroll
            for (int t = 0; t < 8; t++) {
                ull h01, h23, f01, f23;
                LDS2X64(h01, h23, hb); hb += 16;
                LDS2X64(f01, f23, f0b); f0b += 16;
                FFMA2(ag0, h01, f01, ag0);
                FFMA2(ag0, h23, f23, ag0);
                LDS2X64(f01, f23, f1b); f1b += 16;
                FFMA2(ag1, h01, f01, ag1);
                FFMA2(ag1, h23, f23, ag1);
                LDS2X64(f01, f23, f2b); f2b += 16;
                FFMA2(ag2, h01, f01, ag2);
                FFMA2(ag2, h23, f23, ag2);
            }
            float x0, x1;
            float* pb = Pb + wl * 128 + s * 8 + gt * 4;
            UNPK(x0, x1, ag0); pb[0] = x0 + x1;
            UNPK(x0, x1, ag1); pb[1] = x0 + x1;
            UNPK(x0, x1, ag2); pb[2] = x0 + x1;
        }
        LANE_BAR(barid);

        if (act) {
            int slot = gL + (gL >= 3 ? 1 : 0);
            float l1 = CBs[gL] + K1s[par * 128 + sL * 8 + gL] - g_Q1[nn * 8 + gL]
                     + Pb[0 * 128 + sL * 8 + slot]
                     + Pb[1 * 128 + sL * 8 + slot]
                     + Pb[2 * 128 + sL * 8 + slot];
            whes[sL * 8 + gL] = fmaxf(l1, 0.f);
        }
        LANE_BAR(barid);

        if (act) {
            float l2 = bw2s[gL];
            #pragma unroll
            for (int gg = 0; gg < 6; gg++)
                l2 += whes[sL * 8 + gg] * Ww2s[gg * 6 + gL];
            float mx = l2;
            #pragma unroll
            for (int off = 8; off >= 1; off >>= 1)
                mx = fmaxf(mx, __shfl_xor_sync(0xffffffffu, mx, off, 16));
            float e  = __expf(l2 - mx);
            float em = e * masks[par * 16 + sL];
            float ss = e, ms = em;
            #pragma unroll
            for (int off = 8; off >= 1; off >>= 1) {
                ss += __shfl_xor_sync(0xffffffffu, ss, off, 16);
                ms += __shfl_xor_sync(0xffffffffu, ms, off, 16);
            }
            l2w[sL * 8 + gL] = em / ss;
            if (sL == 0) swv[gL] = ms / ss;
        }
        LANE_BAR(barid);

        load_ph1((it + gridDim.x) * 4 + pp, par ^ 1);

        if (act) {
            ull A01 = 0ULL, A23 = 0ULL, A45 = 0ULL;
            unsigned lb = lw_b;
            #pragma unroll
            for (int s = 0; s < 16; s++) {
                ull w01, w23, w45, w67;
                LDS2X64(w01, w23, lb);
                LDS2X64(w45, w67, lb + 16);
                lb += 32;
                ull hd; DUP2(hd, h[s]);
                FFMA2(A01, hd, w01, A01);
                FFMA2(A23, hd, w23, A23);
                FFMA2(A45, hd, w45, A45);
            }
            float A0, A1, A2, A3, A4, A5;
            UNPK(A0, A1, A01);
            UNPK(A2, A3, A23);
            UNPK(A4, A5, A45);
            At[0 * 100 + jr] = A0; At[1 * 100 + jr] = A1; At[2 * 100 + jr] = A2;
            At[3 * 100 + jr] = A3; At[4 * 100 + jr] = A4; At[5 * 100 + jr] = A5;
        }
        __syncthreads();

        {
            int c = jr, g = jr >> 4, j0 = pp * 24;
            ull pt2[4] = {0ULL, 0ULL, 0ULL, 0ULL};
            unsigned wb = wp2_b + (c * 100 + j0) * 4;
            unsigned ab0 = sb + 4 * (SH_LANE + 0 * LZ + L_HT) + (g * 100 + j0) * 4;
            unsigned ab1 = sb + 4 * (SH_LANE + 1 * LZ + L_HT) + (g * 100 + j0) * 4;
            unsigned ab2 = sb + 4 * (SH_LANE + 2 * LZ + L_HT) + (g * 100 + j0) * 4;
            unsigned ab3 = sb + 4 * (SH_LANE + 3 * LZ + L_HT) + (g * 100 + j0) * 4;
            #pragma unroll
            for (int t = 0; t < 6; t++) {
                ull w01, w23, a01, a23;
                LDS2X64(w01, w23, wb); wb += 16;
                LDS2X64(a01, a23, ab0); ab0 += 16;
                FFMA2(pt2[0], w01, a01, pt2[0]);
                FFMA2(pt2[0], w23, a23, pt2[0]);
                LDS2X64(a01, a23, ab1); ab1 += 16;
                FFMA2(pt2[1], w01, a01, pt2[1]);
                FFMA2(pt2[1], w23, a23, pt2[1]);
                LDS2X64(a01, a23, ab2); ab2 += 16;
                FFMA2(pt2[2], w01, a01, pt2[2]);
                FFMA2(pt2[2], w23, a23, pt2[2]);
                LDS2X64(a01, a23, ab3); ab3 += 16;
                FFMA2(pt2[3], w01, a01, pt2[3]);
                FFMA2(pt2[3], w23, a23, pt2[3]);
            }
            #pragma unroll
            for (int p = 0; p < 4; p++) {
                float lo, hi;
                UNPK(lo, hi, pt2[p]);
                part[(pp * 4 + p) * 96 + c] = lo + hi;
            }
        }
        __syncthreads();

        if (act) {
            int c = jr, g = jr >> 4;
            const int* idq = (const int*)(lzone + L_IDX) + par * 16;
            float o = bp2s[c] * swv[g];
            o += part[(0 * 4 + pp) * 96 + c] + part[(1 * 4 + pp) * 96 + c]
               + part[(2 * 4 + pp) * 96 + c] + part[(3 * 4 + pp) * 96 + c];
            float vv[16];
            #pragma unroll
            for (int s = 0; s < 16; s++)
                vv[s] = g_v[idq[s] * 96 + c];
            #pragma unroll
            for (int s = 0; s < 16; s++)
                o += vv[s] * l2w[s * 8 + g];
            out[nn * 96 + c] = o;
        }
        par ^= 1;
    }
}

extern "C" void kernel_launch(void* const* d_in, const int* in_sizes, int n_in,
                              void* d_out, int out_size) {
    const float* feat  = (const float*)d_in[0];
    const float* coord = (const float*)d_in[1];
    const int*   ref   = (const int*)d_in[2];
    const float* Wq    = (const float*)d_in[3];
    const float* bq    = (const float*)d_in[4];
    const float* gq    = (const float*)d_in[5];
    const float* betaq = (const float*)d_in[6];
    const float* Wk    = (const float*)d_in[7];
    const float* bk    = (const float*)d_in[8];
    const float* gk    = (const float*)d_in[9];
    const float* betak = (const float*)d_in[10];
    const float* Wv    = (const float*)d_in[11];
    const float* bv    = (const float*)d_in[12];
    const float* Wp1   = (const float*)d_in[13];
    const float* bp1   = (const float*)d_in[14];
    const float* gp    = (const float*)d_in[15];
    const float* betap = (const float*)d_in[16];
    const float* Wp2   = (const float*)d_in[17];
    const float* bp2   = (const float*)d_in[18];
    const float* Ww1   = (const float*)d_in[19];
    const float* bw1   = (const float*)d_in[20];
    const float* gw    = (const float*)d_in[21];
    const float* betaw = (const float*)d_in[22];
    const float* Ww2   = (const float*)d_in[23];
    const float* bw2   = (const float*)d_in[24];

    int n = in_sizes[1] / 3;

    int smA = A_FLOATS * (int)sizeof(float);
    int smB = B_FLOATS * (int)sizeof(float);
    cudaFuncSetAttribute(qkv_kernel,  cudaFuncAttributeMaxDynamicSharedMemorySize, smA);
    cudaFuncSetAttribute(attn_kernel, cudaFuncAttributeMaxDynamicSharedMemorySize, smB);

    int blocksA = (n + 63) / 64;
    qkv_kernel<<<blocksA, 192, smA>>>(feat, coord, Wq, bq, gq, betaq,
                                      Wk, bk, gk, betak, Wv, bv, Ww1, gw, n);

    int occ = 0;
    cudaOccupancyMaxActiveBlocksPerMultiprocessor(&occ, attn_kernel, 384, smB);
    if (occ < 1) occ = 1;
    int nsm = 0;
    cudaDeviceGetAttribute(&nsm, cudaDevAttrMultiProcessorCount, 0);
    if (nsm <= 0) nsm = 148;
    int blocksB = occ * nsm;
    int quads = (n + 3) / 4;
    if (blocksB > quads) blocksB = quads;

    attn_kernel<<<blocksB, 384, smB>>>(ref,
                                       Wp1, bp1, gp, betap, Wp2, bp2,
                                       Ww1, bw1, gw, betaw, Ww2, bw2,
                                       (float*)d_out, n);
}